// round 2
// baseline (speedup 1.0000x reference)
#include <cuda_runtime.h>
#include <cuda_bf16.h>
#include <math.h>

#define S_LEN 2048
#define DIM 1024
#define NH 16
#define KVH 4
#define HD 64
#define KVDIM 256
#define NTOT 1792   // 1024 (q) + 256 (k) + 256 (v) + 256 (g)

// ---------------- device scratch (no allocations allowed) ----------------
__device__ float g_qkvg[S_LEN * NTOT];       // [S, 1792]
__device__ float g_q[NH * S_LEN * HD];       // [H][S][64] post norm/rotary/gain
__device__ float g_k[KVH * S_LEN * HD];      // [KVH][S][64]
__device__ float g_v[KVH * S_LEN * HD];      // gated V
__device__ float g_a[NH * S_LEN * HD];       // attention out: half0 in d<32, half1 in d>=32
__device__ float g_y[S_LEN * DIM];           // combined, token-major

// ---------------- SGEMM: C[M,N] = A[M,K] @ B[N,K]^T ----------------------
// B is a virtual concatenation of up to 4 row-major [n_i, K] matrices.
// 128x128 block tile, BK=8, 256 threads, 8x8 register microtile,
// register prefetch of the next K-slab to hide global latency.
__global__ __launch_bounds__(256) void sgemm_abt(
    const float* __restrict__ A,
    float* __restrict__ C, int ldc, int K,
    const float* __restrict__ B0, const float* __restrict__ B1,
    const float* __restrict__ B2, const float* __restrict__ B3,
    int n0, int n1, int n2)
{
    __shared__ float As[8][128];
    __shared__ float Bs[8][128];

    const int m0 = blockIdx.y * 128;
    const int nb = blockIdx.x * 128;
    const int t  = threadIdx.x;
    const int lr = t >> 1;            // 0..127: row within tile for loading
    const int lk = (t & 1) << 2;      // 0 or 4: k sub-offset
    const int ty = t >> 4;            // 0..15
    const int tx = t & 15;            // 0..15

    // resolve virtual B row pointer
    const int n = nb + lr;
    const float* brp;
    if      (n < n0) brp = B0 + (size_t)n        * K;
    else if (n < n1) brp = B1 + (size_t)(n - n0) * K;
    else if (n < n2) brp = B2 + (size_t)(n - n1) * K;
    else             brp = B3 + (size_t)(n - n2) * K;

    const float* arp = A + (size_t)(m0 + lr) * K;

    float4 aReg = *(const float4*)(arp + lk);
    float4 bReg = *(const float4*)(brp + lk);

    float acc[8][8];
    #pragma unroll
    for (int i = 0; i < 8; i++)
        #pragma unroll
        for (int j = 0; j < 8; j++) acc[i][j] = 0.0f;

    for (int k0 = 0; k0 < K; k0 += 8) {
        As[lk + 0][lr] = aReg.x; As[lk + 1][lr] = aReg.y;
        As[lk + 2][lr] = aReg.z; As[lk + 3][lr] = aReg.w;
        Bs[lk + 0][lr] = bReg.x; Bs[lk + 1][lr] = bReg.y;
        Bs[lk + 2][lr] = bReg.z; Bs[lk + 3][lr] = bReg.w;
        __syncthreads();

        const int kn = k0 + 8;
        if (kn < K) {
            aReg = *(const float4*)(arp + kn + lk);
            bReg = *(const float4*)(brp + kn + lk);
        }

        #pragma unroll
        for (int kk = 0; kk < 8; kk++) {
            float ar[8], br[8];
            *(float4*)&ar[0] = *(const float4*)&As[kk][ty * 8];
            *(float4*)&ar[4] = *(const float4*)&As[kk][ty * 8 + 4];
            *(float4*)&br[0] = *(const float4*)&Bs[kk][tx * 8];
            *(float4*)&br[4] = *(const float4*)&Bs[kk][tx * 8 + 4];
            #pragma unroll
            for (int i = 0; i < 8; i++)
                #pragma unroll
                for (int j = 0; j < 8; j++)
                    acc[i][j] += ar[i] * br[j];
        }
        __syncthreads();
    }

    #pragma unroll
    for (int i = 0; i < 8; i++) {
        float* crow = C + (size_t)(m0 + ty * 8 + i) * ldc + nb + tx * 8;
        ((float4*)crow)[0] = make_float4(acc[i][0], acc[i][1], acc[i][2], acc[i][3]);
        ((float4*)crow)[1] = make_float4(acc[i][4], acc[i][5], acc[i][6], acc[i][7]);
    }
}

// ---------------- postprocess: V-gate, RMS-norm, rotary, q_gain ----------
// grid (S, 21), block 64. unit<16: q head; unit<20: k head; unit==20: v gate.
__global__ __launch_bounds__(64) void postproc(const float* __restrict__ q_gain)
{
    const int m    = blockIdx.x;
    const int unit = blockIdx.y;
    const int t    = threadIdx.x;
    const float* row = g_qkvg + (size_t)m * NTOT;

    if (unit == 20) {
        #pragma unroll
        for (int i = t; i < KVDIM; i += 64) {
            float v = row[1280 + i];
            float g = row[1536 + i];
            float vg = v / (1.0f + expf(-g));
            g_v[(size_t)(i >> 6) * (S_LEN * HD) + (size_t)m * HD + (i & 63)] = vg;
        }
        return;
    }

    const bool isq = unit < 16;
    const int h    = isq ? unit : unit - 16;
    const int col0 = isq ? h * HD : 1024 + h * HD;

    float x = row[col0 + t];

    // mean(x^2) over the 64-wide head
    float ss = x * x;
    #pragma unroll
    for (int o = 16; o > 0; o >>= 1) ss += __shfl_xor_sync(0xffffffffu, ss, o);
    __shared__ float s2[2];
    __shared__ float xs[64];
    if ((t & 31) == 0) s2[t >> 5] = ss;
    __syncthreads();
    const float tot = s2[0] + s2[1];
    const float xn  = x * rsqrtf(tot * (1.0f / 64.0f) + 1.1920929e-7f); // fp32 eps
    xs[t] = xn;
    __syncthreads();

    const float gain = isq ? q_gain[h] : 1.0f;
    float* dst = (isq ? g_q + (size_t)h * (S_LEN * HD)
                      : g_k + (size_t)h * (S_LEN * HD)) + (size_t)m * HD;

    if (t < 32) {
        const float x1 = xs[t], x2 = xs[t + 32];
        // match reference fp32 rounding: angle = ((2t)/64) * pi_f ; ang = m * angle
        const float angle = ((float)(2 * t) / 64.0f) * 3.14159274101257324f;
        const float ang   = (float)m * angle;
        // accurate range reduction in double, then fp32 trig on small arg
        double a = (double)ang;
        double kq = rint(a * 0.15915494309189535);     // a / (2*pi)
        a -= kq * 6.283185307179586;
        float c, sn;
        sincosf((float)a, &sn, &c);
        const float radius = 1.0f / (1.0f + (float)m * 0.01f);
        c *= radius; sn *= radius;
        dst[t]      = ( x1 * c + x2 * sn) * gain;
        dst[t + 32] = (-x1 * sn + x2 * c) * gain;
    }
}

// ---------------- flash attention, fp32, per-half (d=32) -----------------
// grid (32 q-tiles, 16 heads, 2 halves), block 64: one thread per query row.
__global__ __launch_bounds__(64) void attn_kernel()
{
    const int qt   = gridDim.x - 1 - blockIdx.x;  // big tiles first (tail balance)
    const int h    = blockIdx.y;
    const int half = blockIdx.z;
    const int kvh  = h >> 2;
    const int t    = threadIdx.x;
    const int qrow = qt * 64 + t;

    const float SCALE = 0.17677669529663688f;     // 1/sqrt(32)

    const float* qptr = g_q + ((size_t)h * S_LEN + qrow) * HD + half * 32;
    float q[32];
    #pragma unroll
    for (int i = 0; i < 8; i++) {
        float4 v4 = ((const float4*)qptr)[i];
        q[4*i] = v4.x; q[4*i+1] = v4.y; q[4*i+2] = v4.z; q[4*i+3] = v4.w;
    }

    float acc[32];
    #pragma unroll
    for (int d = 0; d < 32; d++) acc[d] = 0.0f;
    float mrun = -INFINITY, lrun = 0.0f;

    __shared__ float ks[32][36];
    __shared__ float vs[32][36];

    const float* kbase = g_k + (size_t)kvh * S_LEN * HD + half * 32;
    const float* vbase = g_v + (size_t)kvh * S_LEN * HD + half * 32;

    const int lr = t >> 1;            // 0..31: key row to load
    const int lc = (t & 1) << 4;      // 0 or 16

    const int ntiles = 2 * qt + 2;    // keys 0 .. qt*64+63
    for (int kt = 0; kt < ntiles; kt++) {
        const float* krow = kbase + (size_t)(kt * 32 + lr) * HD + lc;
        const float* vrow = vbase + (size_t)(kt * 32 + lr) * HD + lc;
        #pragma unroll
        for (int i = 0; i < 4; i++) {
            *(float4*)&ks[lr][lc + 4*i] = *(const float4*)(krow + 4*i);
            *(float4*)&vs[lr][lc + 4*i] = *(const float4*)(vrow + 4*i);
        }
        __syncthreads();

        float sc[32];
        #pragma unroll
        for (int j = 0; j < 32; j++) {
            float s = 0.0f;
            #pragma unroll
            for (int dv = 0; dv < 8; dv++) {
                float4 kv = *(const float4*)&ks[j][4*dv];  // broadcast LDS
                s += q[4*dv]   * kv.x;
                s += q[4*dv+1] * kv.y;
                s += q[4*dv+2] * kv.z;
                s += q[4*dv+3] * kv.w;
            }
            sc[j] = (kt * 32 + j > qrow) ? -INFINITY : s * SCALE;
        }

        float mt = sc[0];
        #pragma unroll
        for (int j = 1; j < 32; j++) mt = fmaxf(mt, sc[j]);
        const float mnew = fmaxf(mrun, mt);
        const float corr = expf(mrun - mnew);
        lrun *= corr;
        #pragma unroll
        for (int d = 0; d < 32; d++) acc[d] *= corr;

        #pragma unroll
        for (int j = 0; j < 32; j++) {
            const float p = expf(sc[j] - mnew);
            lrun += p;
            #pragma unroll
            for (int dv = 0; dv < 8; dv++) {
                float4 vv = *(const float4*)&vs[j][4*dv];  // broadcast LDS
                acc[4*dv]   += p * vv.x;
                acc[4*dv+1] += p * vv.y;
                acc[4*dv+2] += p * vv.z;
                acc[4*dv+3] += p * vv.w;
            }
        }
        mrun = mnew;
        __syncthreads();
    }

    const float inv = 1.0f / lrun;
    float* optr = g_a + ((size_t)h * S_LEN + qrow) * HD + half * 32;
    #pragma unroll
    for (int i = 0; i < 8; i++) {
        ((float4*)optr)[i] = make_float4(acc[4*i] * inv, acc[4*i+1] * inv,
                                         acc[4*i+2] * inv, acc[4*i+3] * inv);
    }
}

// ---------------- differential combine: y = [a1 - l*a2, a1 + l*a2] -------
__global__ __launch_bounds__(512) void combine(const float* __restrict__ lambda_p)
{
    const int m = blockIdx.x;
    const int t = threadIdx.x;        // 512: h = t/32, j = t%32
    const int h = t >> 5, j = t & 31;
    const float lam = lambda_p[h];
    const float* ap = g_a + ((size_t)h * S_LEN + m) * HD;
    const float a1 = ap[j], a2 = ap[j + 32];
    float* yr = g_y + (size_t)m * DIM + h * HD;
    yr[j]      = a1 - lam * a2;
    yr[j + 32] = a1 + lam * a2;
}

// ---------------- launch ---------------------------------------------------
extern "C" void kernel_launch(void* const* d_in, const int* in_sizes, int n_in,
                              void* d_out, int out_size)
{
    const float* x        = (const float*)d_in[0];
    const float* Wq       = (const float*)d_in[1];
    const float* Wk       = (const float*)d_in[2];
    const float* Wv       = (const float*)d_in[3];
    const float* Wg       = (const float*)d_in[4];
    const float* Wo       = (const float*)d_in[5];
    const float* q_gain   = (const float*)d_in[6];
    const float* lambda_p = (const float*)d_in[7];
    float* out = (float*)d_out;

    float *qkvg_p, *y_p;
    cudaGetSymbolAddress((void**)&qkvg_p, g_qkvg);
    cudaGetSymbolAddress((void**)&y_p, g_y);

    // 1) fused QKVG projection: [2048,1792] = x @ [Wq;Wk;Wv;Wg]^T
    dim3 g1(NTOT / 128, S_LEN / 128);
    sgemm_abt<<<g1, 256>>>(x, qkvg_p, NTOT, DIM,
                           Wq, Wk, Wv, Wg, 1024, 1280, 1536);

    // 2) gate V, RMS-norm + rotary + gain for Q/K
    postproc<<<dim3(S_LEN, 21), 64>>>(q_gain);

    // 3) split-half causal flash attention
    attn_kernel<<<dim3(S_LEN / 64, NH, 2), 64>>>();

    // 4) differential combine
    combine<<<S_LEN, 512>>>(lambda_p);

    // 5) output projection
    dim3 g2(DIM / 128, S_LEN / 128);
    sgemm_abt<<<g2, 256>>>(y_p, out, DIM, DIM,
                           Wo, Wo, Wo, Wo, DIM, DIM, DIM);
}

// round 4
// speedup vs baseline: 2.3617x; 2.3617x over previous
#include <cuda_runtime.h>
#include <cuda_bf16.h>
#include <math.h>
#include <stdint.h>

#define S_LEN 2048
#define DIM 1024
#define NH 16
#define KVH 4
#define HD 64
#define NTOT 1792
typedef unsigned long long u64;

__device__ float g_qkvg[S_LEN * NTOT];
__device__ float g_q[NH * S_LEN * HD];
__device__ float g_k[KVH * S_LEN * HD];
__device__ float g_v[KVH * S_LEN * HD];
__device__ float g_a[NH * S_LEN * HD];
__device__ __nv_bfloat16 g_xhi[S_LEN * DIM],  g_xlo[S_LEN * DIM];
__device__ __nv_bfloat16 g_whi[NTOT * DIM],   g_wlo[NTOT * DIM];
__device__ __nv_bfloat16 g_wohi[DIM * DIM],   g_wolo[DIM * DIM];
__device__ __nv_bfloat16 g_yhi[S_LEN * DIM],  g_ylo[S_LEN * DIM];

__device__ __forceinline__ uint32_t smem_u32(const void* p) {
    uint32_t a;
    asm("{ .reg .u64 t; cvta.to.shared.u64 t, %1; cvt.u32.u64 %0, t; }" : "=r"(a) : "l"(p));
    return a;
}
#define CP16(sm, gp) asm volatile("cp.async.cg.shared.global [%0], [%1], 16;" :: "r"(sm), "l"(gp))
#define LDSM4(r, addr) \
    asm volatile("ldmatrix.sync.aligned.m8n8.x4.shared.b16 {%0,%1,%2,%3}, [%4];" \
        : "=r"((r)[0]), "=r"((r)[1]), "=r"((r)[2]), "=r"((r)[3]) : "r"(addr))
#define MMA16816(d, a, b0, b1) \
    asm volatile("mma.sync.aligned.m16n8k16.row.col.f32.bf16.bf16.f32 " \
        "{%0,%1,%2,%3}, {%4,%5,%6,%7}, {%8,%9}, {%0,%1,%2,%3};" \
        : "+f"((d)[0]), "+f"((d)[1]), "+f"((d)[2]), "+f"((d)[3]) \
        : "r"((a)[0]), "r"((a)[1]), "r"((a)[2]), "r"((a)[3]), "r"(b0), "r"(b1))
#define FMA2(d, a, b, c) asm("fma.rn.f32x2 %0, %1, %2, %3;" : "=l"(d) : "l"(a), "l"(b), "l"(c))
#define MUL2(d, a, b)    asm("mul.rn.f32x2 %0, %1, %2;"     : "=l"(d) : "l"(a), "l"(b))
__device__ __forceinline__ u64 pk2(float x, float y) {
    u64 r; asm("mov.b64 %0, {%1, %2};" : "=l"(r) : "f"(x), "f"(y)); return r;
}
__device__ __forceinline__ float2 upk2(u64 v) {
    float2 r; asm("mov.b64 {%0, %1}, %2;" : "=f"(r.x), "=f"(r.y) : "l"(v)); return r;
}

// -------- fp32 -> bf16 hi/lo split --------
__global__ __launch_bounds__(256) void conv_split(
    const float* __restrict__ s, __nv_bfloat16* __restrict__ hi,
    __nv_bfloat16* __restrict__ lo, int n4)
{
    int i = blockIdx.x * 256 + threadIdx.x;
    if (i >= n4) return;
    float4 v = ((const float4*)s)[i];
    __nv_bfloat16 a0 = __float2bfloat16(v.x), a1 = __float2bfloat16(v.y);
    __nv_bfloat16 a2 = __float2bfloat16(v.z), a3 = __float2bfloat16(v.w);
    __nv_bfloat162 h0, h1, l0, l1;
    h0.x = a0; h0.y = a1; h1.x = a2; h1.y = a3;
    l0.x = __float2bfloat16(v.x - __bfloat162float(a0));
    l0.y = __float2bfloat16(v.y - __bfloat162float(a1));
    l1.x = __float2bfloat16(v.z - __bfloat162float(a2));
    l1.y = __float2bfloat16(v.w - __bfloat162float(a3));
    ((__nv_bfloat162*)hi)[2*i] = h0; ((__nv_bfloat162*)hi)[2*i+1] = h1;
    ((__nv_bfloat162*)lo)[2*i] = l0; ((__nv_bfloat162*)lo)[2*i+1] = l1;
}

// -------- HMMA bf16x3 GEMM: C[M,N] = A[M,K] @ B[N,K]^T, fp32-accurate --------
// 128x128 block tile, BK=64, 256 threads (8 warps, warp tile 64x32),
// double-buffered cp.async. smem tiles padded to 72 bf16/row (144B).
#define AST   18432                 // one tile: 128 rows * 144B
#define STG_B (4 * AST)             // Ahi,Alo,Bhi,Blo
#define GSMEM (2 * STG_B)           // 147456

__device__ __forceinline__ void g_load_stage(
    uint32_t sb, const char* pAhi, const char* pAlo,
    const char* pBhi, const char* pBlo, int t, int s)
{
    const size_t gk = (size_t)s * 128;
    #pragma unroll
    for (int j = 0; j < 4; j++) {
        const int c = t + 256 * j;
        const int row = c >> 3, kc = c & 7;
        const size_t go = (size_t)row * 2048 + gk + kc * 16;
        const uint32_t so = row * 144 + kc * 16;
        CP16(sb +           so, pAhi + go);
        CP16(sb +   AST  +  so, pAlo + go);
        CP16(sb + 2*AST  +  so, pBhi + go);
        CP16(sb + 3*AST  +  so, pBlo + go);
    }
    asm volatile("cp.async.commit_group;" ::: "memory");
}

__global__ __launch_bounds__(256) void gemm_hmma3(
    const __nv_bfloat16* __restrict__ Ahi, const __nv_bfloat16* __restrict__ Alo,
    const __nv_bfloat16* __restrict__ Bhi, const __nv_bfloat16* __restrict__ Blo,
    float* __restrict__ C, int ldc)
{
    extern __shared__ char sm[];
    const int t = threadIdx.x, wid = t >> 5, lane = t & 31;
    const int m0 = blockIdx.y * 128, nb = blockIdx.x * 128;
    const uint32_t smb = smem_u32(sm);

    const char* pAhi = (const char*)Ahi + (size_t)m0 * 2048;
    const char* pAlo = (const char*)Alo + (size_t)m0 * 2048;
    const char* pBhi = (const char*)Bhi + (size_t)nb * 2048;
    const char* pBlo = (const char*)Blo + (size_t)nb * 2048;

    const int warp_m = (wid & 1) * 64;
    const int warp_n = (wid >> 1) * 32;

    // ldmatrix lane address components
    const int a_m  = lane & 15;             // A: row within 16
    const int a_kb = lane >> 4;             // A: k-block 0/1
    const int b_n  = (lane & 7) + ((lane >> 4) & 1) * 8;  // B: n within 16
    const int b_kb = (lane >> 3) & 1;       // B: k-block 0/1

    float acc[4][4][4];
    #pragma unroll
    for (int im = 0; im < 4; im++)
        #pragma unroll
        for (int jn = 0; jn < 4; jn++)
            #pragma unroll
            for (int c = 0; c < 4; c++) acc[im][jn][c] = 0.0f;

    g_load_stage(smb,         pAhi, pAlo, pBhi, pBlo, t, 0);
    g_load_stage(smb + STG_B, pAhi, pAlo, pBhi, pBlo, t, 1);

    #pragma unroll 1
    for (int s = 0; s < 16; s++) {
        const int b = s & 1;
        if (s < 15) asm volatile("cp.async.wait_group 1;" ::: "memory");
        else        asm volatile("cp.async.wait_group 0;" ::: "memory");
        __syncthreads();

        const uint32_t sb = smb + b * STG_B;
        #pragma unroll
        for (int kk = 0; kk < 4; kk++) {
            const uint32_t k0 = kk * 16;
            uint32_t ahi[4][4], alo[4][4], bhi[2][4], blo[2][4];
            const uint32_t aoff = (warp_m + a_m) * 144 + (k0 + a_kb * 8) * 2;
            #pragma unroll
            for (int im = 0; im < 4; im++) {
                LDSM4(ahi[im], sb +        aoff + im * (16 * 144));
                LDSM4(alo[im], sb + AST  + aoff + im * (16 * 144));
            }
            #pragma unroll
            for (int j2 = 0; j2 < 2; j2++) {
                const uint32_t boff = (warp_n + j2 * 16 + b_n) * 144 + (k0 + b_kb * 8) * 2;
                LDSM4(bhi[j2], sb + 2*AST + boff);
                LDSM4(blo[j2], sb + 3*AST + boff);
            }
            #pragma unroll
            for (int im = 0; im < 4; im++)
                #pragma unroll
                for (int jn = 0; jn < 4; jn++) {
                    const int j2 = jn >> 1, jr = (jn & 1) * 2;
                    MMA16816(acc[im][jn], ahi[im], bhi[j2][jr], bhi[j2][jr + 1]);
                    MMA16816(acc[im][jn], ahi[im], blo[j2][jr], blo[j2][jr + 1]);
                    MMA16816(acc[im][jn], alo[im], bhi[j2][jr], bhi[j2][jr + 1]);
                }
        }
        __syncthreads();
        if (s + 2 < 16) g_load_stage(sb, pAhi, pAlo, pBhi, pBlo, t, s + 2);
    }

    const int r0 = lane >> 2, c0 = (lane & 3) * 2;
    #pragma unroll
    for (int im = 0; im < 4; im++)
        #pragma unroll
        for (int jn = 0; jn < 4; jn++) {
            const int row = m0 + warp_m + im * 16 + r0;
            const int col = nb + warp_n + jn * 8 + c0;
            *(float2*)&C[(size_t)row * ldc + col] =
                make_float2(acc[im][jn][0], acc[im][jn][1]);
            *(float2*)&C[(size_t)(row + 8) * ldc + col] =
                make_float2(acc[im][jn][2], acc[im][jn][3]);
        }
}

// -------- postprocess: V-gate, RMS-norm, rotary, q_gain --------
__global__ __launch_bounds__(64) void postproc(const float* __restrict__ q_gain)
{
    const int m = blockIdx.x, unit = blockIdx.y, t = threadIdx.x;
    const float* row = g_qkvg + (size_t)m * NTOT;
    if (unit == 20) {
        #pragma unroll
        for (int i = t; i < 256; i += 64) {
            float v = row[1280 + i], g = row[1536 + i];
            g_v[(size_t)(i >> 6) * (S_LEN * HD) + (size_t)m * HD + (i & 63)]
                = v / (1.0f + expf(-g));
        }
        return;
    }
    const bool isq = unit < 16;
    const int h = isq ? unit : unit - 16;
    const int col0 = isq ? h * HD : 1024 + h * HD;
    float x = row[col0 + t];
    float ss = x * x;
    #pragma unroll
    for (int o = 16; o > 0; o >>= 1) ss += __shfl_xor_sync(0xffffffffu, ss, o);
    __shared__ float s2[2];
    __shared__ float xs[64];
    if ((t & 31) == 0) s2[t >> 5] = ss;
    __syncthreads();
    const float xn = x * rsqrtf((s2[0] + s2[1]) * (1.0f / 64.0f) + 1.1920929e-7f);
    xs[t] = xn;
    __syncthreads();
    const float gain = isq ? q_gain[h] : 1.0f;
    float* dst = (isq ? g_q + (size_t)h * (S_LEN * HD)
                      : g_k + (size_t)h * (S_LEN * HD)) + (size_t)m * HD;
    if (t < 32) {
        const float x1 = xs[t], x2 = xs[t + 32];
        const float angle = ((float)(2 * t) / 64.0f) * 3.14159274101257324f;
        const float ang = (float)m * angle;
        double a = (double)ang;
        a -= rint(a * 0.15915494309189535) * 6.283185307179586;
        float c, sn;
        sincosf((float)a, &sn, &c);
        const float radius = 1.0f / (1.0f + (float)m * 0.01f);
        c *= radius; sn *= radius;
        dst[t]      = ( x1 * c + x2 * sn) * gain;
        dst[t + 32] = (-x1 * sn + x2 * c) * gain;
    }
}

// -------- flash attention, packed f32x2, per 32-dim half --------
__global__ __launch_bounds__(128) void attn2()
{
    const int qt = gridDim.x - 1 - blockIdx.x;
    const int h = blockIdx.y, half = blockIdx.z, kvh = h >> 2;
    const int t = threadIdx.x;
    const int qrow = qt * 128 + t;
    __shared__ float ks[32][36];
    __shared__ float vs[32][36];
    const float SCALE = 0.17677669529663688f;

    const float* qp = g_q + ((size_t)h * S_LEN + qrow) * HD + half * 32;
    u64 q2[16];
    #pragma unroll
    for (int i = 0; i < 8; i++) {
        ulonglong2 v = ((const ulonglong2*)qp)[i];
        q2[2*i] = v.x; q2[2*i+1] = v.y;
    }
    {
        const u64 s2 = pk2(SCALE, SCALE);
        #pragma unroll
        for (int i = 0; i < 16; i++) MUL2(q2[i], q2[i], s2);
    }
    u64 acc2[16];
    #pragma unroll
    for (int i = 0; i < 16; i++) acc2[i] = 0ull;
    float mrun = -INFINITY, lrun = 0.0f;

    const float* kbase = g_k + (size_t)kvh * S_LEN * HD + half * 32;
    const float* vbase = g_v + (size_t)kvh * S_LEN * HD + half * 32;
    const int lr = t >> 2, lseg = (t & 3) * 8;

    const int ntiles = 4 * qt + 4;
    for (int kt = 0; kt < ntiles; kt++) {
        const float* kr = kbase + (size_t)(kt * 32 + lr) * HD + lseg;
        const float* vr = vbase + (size_t)(kt * 32 + lr) * HD + lseg;
        *(float4*)&ks[lr][lseg]     = *(const float4*)kr;
        *(float4*)&ks[lr][lseg + 4] = *(const float4*)(kr + 4);
        *(float4*)&vs[lr][lseg]     = *(const float4*)vr;
        *(float4*)&vs[lr][lseg + 4] = *(const float4*)(vr + 4);
        __syncthreads();

        const int limit = qrow - kt * 32;
        float scv[32];
        float mt = -INFINITY;
        #pragma unroll
        for (int j = 0; j < 32; j++) {
            u64 sa = 0ull, sb = 0ull;
            #pragma unroll
            for (int i = 0; i < 4; i++) {
                ulonglong2 ka = *(const ulonglong2*)&ks[j][8*i];
                ulonglong2 kb = *(const ulonglong2*)&ks[j][8*i + 4];
                FMA2(sa, q2[4*i],     ka.x, sa);
                FMA2(sb, q2[4*i + 1], ka.y, sb);
                FMA2(sa, q2[4*i + 2], kb.x, sa);
                FMA2(sb, q2[4*i + 3], kb.y, sb);
            }
            float2 fa = upk2(sa), fb = upk2(sb);
            float s = (fa.x + fb.x) + (fa.y + fb.y);
            s = (j <= limit) ? s : -INFINITY;
            scv[j] = s;
            mt = fmaxf(mt, s);
        }
        const float mnew = fmaxf(mrun, mt);
        const float corr = __expf(mrun - mnew);
        lrun *= corr;
        {
            const u64 c2 = pk2(corr, corr);
            #pragma unroll
            for (int i = 0; i < 16; i++) MUL2(acc2[i], acc2[i], c2);
        }
        float ls = 0.0f;
        #pragma unroll
        for (int j = 0; j < 32; j++) {
            const float p = __expf(scv[j] - mnew);
            ls += p;
            const u64 p2 = pk2(p, p);
            #pragma unroll
            for (int i = 0; i < 8; i++) {
                ulonglong2 vv = *(const ulonglong2*)&vs[j][4*i];
                FMA2(acc2[2*i],     p2, vv.x, acc2[2*i]);
                FMA2(acc2[2*i + 1], p2, vv.y, acc2[2*i + 1]);
            }
        }
        lrun += ls;
        mrun = mnew;
        __syncthreads();
    }
    const float inv = 1.0f / lrun;
    const u64 inv2 = pk2(inv, inv);
    float* op = g_a + ((size_t)h * S_LEN + qrow) * HD + half * 32;
    #pragma unroll
    for (int i = 0; i < 8; i++) {
        u64 o0, o1;
        MUL2(o0, acc2[2*i], inv2);
        MUL2(o1, acc2[2*i + 1], inv2);
        ulonglong2 ov; ov.x = o0; ov.y = o1;
        ((ulonglong2*)op)[i] = ov;
    }
}

// -------- differential combine -> bf16 hi/lo --------
__global__ __launch_bounds__(512) void combine2(const float* __restrict__ lambda_p)
{
    const int m = blockIdx.x, t = threadIdx.x;
    const int h = t >> 5, j = t & 31;
    const float lam = lambda_p[h];
    const float* ap = g_a + ((size_t)h * S_LEN + m) * HD;
    const float a1 = ap[j], a2 = ap[j + 32];
    const float y1 = a1 - lam * a2, y2 = a1 + lam * a2;
    const size_t o1 = (size_t)m * DIM + h * HD + j, o2 = o1 + 32;
    __nv_bfloat16 h1 = __float2bfloat16(y1), h2 = __float2bfloat16(y2);
    g_yhi[o1] = h1; g_ylo[o1] = __float2bfloat16(y1 - __bfloat162float(h1));
    g_yhi[o2] = h2; g_ylo[o2] = __float2bfloat16(y2 - __bfloat162float(h2));
}

extern "C" void kernel_launch(void* const* d_in, const int* in_sizes, int n_in,
                              void* d_out, int out_size)
{
    const float* x        = (const float*)d_in[0];
    const float* Wq       = (const float*)d_in[1];
    const float* Wk       = (const float*)d_in[2];
    const float* Wv       = (const float*)d_in[3];
    const float* Wg       = (const float*)d_in[4];
    const float* Wo       = (const float*)d_in[5];
    const float* q_gain   = (const float*)d_in[6];
    const float* lambda_p = (const float*)d_in[7];
    float* out = (float*)d_out;

    cudaFuncSetAttribute(gemm_hmma3, cudaFuncAttributeMaxDynamicSharedMemorySize, GSMEM);

    float* qkvg_p;
    __nv_bfloat16 *xhi, *xlo, *whi, *wlo, *wohi, *wolo, *yhi, *ylo;
    cudaGetSymbolAddress((void**)&qkvg_p, g_qkvg);
    cudaGetSymbolAddress((void**)&xhi, g_xhi);   cudaGetSymbolAddress((void**)&xlo, g_xlo);
    cudaGetSymbolAddress((void**)&whi, g_whi);   cudaGetSymbolAddress((void**)&wlo, g_wlo);
    cudaGetSymbolAddress((void**)&wohi, g_wohi); cudaGetSymbolAddress((void**)&wolo, g_wolo);
    cudaGetSymbolAddress((void**)&yhi, g_yhi);   cudaGetSymbolAddress((void**)&ylo, g_ylo);

    conv_split<<<2048, 256>>>(x,  xhi, xlo, 524288);
    conv_split<<<1024, 256>>>(Wq, whi, wlo, 262144);
    conv_split<<<256,  256>>>(Wk, whi + 1024*1024, wlo + 1024*1024, 65536);
    conv_split<<<256,  256>>>(Wv, whi + 1280*1024, wlo + 1280*1024, 65536);
    conv_split<<<256,  256>>>(Wg, whi + 1536*1024, wlo + 1536*1024, 65536);
    conv_split<<<1024, 256>>>(Wo, wohi, wolo, 262144);

    gemm_hmma3<<<dim3(NTOT/128, S_LEN/128), 256, GSMEM>>>(xhi, xlo, whi, wlo, qkvg_p, NTOT);
    postproc<<<dim3(S_LEN, 21), 64>>>(q_gain);
    attn2<<<dim3(S_LEN/128, NH, 2), 128>>>();
    combine2<<<S_LEN, 512>>>(lambda_p);
    gemm_hmma3<<<dim3(DIM/128, S_LEN/128), 256, GSMEM>>>(yhi, ylo, wohi, wolo, out, DIM);
}

// round 5
// speedup vs baseline: 5.0225x; 2.1267x over previous
#include <cuda_runtime.h>
#include <cuda_bf16.h>
#include <math.h>
#include <stdint.h>

#define S_LEN 2048
#define DIM 1024
#define NH 16
#define KVH 4
#define HD 64
#define NTOT 1792

__device__ float g_qkvg[S_LEN * NTOT];
__device__ float g_a[NH * S_LEN * HD];
__device__ __nv_bfloat16 g_xhi[S_LEN * DIM],  g_xlo[S_LEN * DIM];
__device__ __nv_bfloat16 g_whi[NTOT * DIM],   g_wlo[NTOT * DIM];
__device__ __nv_bfloat16 g_wohi[DIM * DIM],   g_wolo[DIM * DIM];
__device__ __nv_bfloat16 g_yhi[S_LEN * DIM],  g_ylo[S_LEN * DIM];
// attention operands, bf16 hi/lo, layout [(head*2+half)][seq][32]
__device__ __nv_bfloat16 g_aqh[NH*2*S_LEN*32], g_aql[NH*2*S_LEN*32];
__device__ __nv_bfloat16 g_akh[KVH*2*S_LEN*32], g_akl[KVH*2*S_LEN*32];
__device__ __nv_bfloat16 g_avh[KVH*2*S_LEN*32], g_avl[KVH*2*S_LEN*32];

__device__ __forceinline__ uint32_t smem_u32(const void* p) {
    uint32_t a;
    asm("{ .reg .u64 t; cvta.to.shared.u64 t, %1; cvt.u32.u64 %0, t; }" : "=r"(a) : "l"(p));
    return a;
}
#define CP16(sm, gp) asm volatile("cp.async.cg.shared.global [%0], [%1], 16;" :: "r"(sm), "l"(gp))
#define LDSM4(r, addr) \
    asm volatile("ldmatrix.sync.aligned.m8n8.x4.shared.b16 {%0,%1,%2,%3}, [%4];" \
        : "=r"((r)[0]), "=r"((r)[1]), "=r"((r)[2]), "=r"((r)[3]) : "r"(addr))
#define LDSM4T(r, addr) \
    asm volatile("ldmatrix.sync.aligned.m8n8.x4.trans.shared.b16 {%0,%1,%2,%3}, [%4];" \
        : "=r"((r)[0]), "=r"((r)[1]), "=r"((r)[2]), "=r"((r)[3]) : "r"(addr))
#define MMA16816(d, a, b0, b1) \
    asm volatile("mma.sync.aligned.m16n8k16.row.col.f32.bf16.bf16.f32 " \
        "{%0,%1,%2,%3}, {%4,%5,%6,%7}, {%8,%9}, {%0,%1,%2,%3};" \
        : "+f"((d)[0]), "+f"((d)[1]), "+f"((d)[2]), "+f"((d)[3]) \
        : "r"((a)[0]), "r"((a)[1]), "r"((a)[2]), "r"((a)[3]), "r"(b0), "r"(b1))
// pack: lower = a, upper = b
#define PACKBF(r, a, b) asm("cvt.rn.bf16x2.f32 %0, %1, %2;" : "=r"(r) : "f"(b), "f"(a))

__device__ __forceinline__ void split_bf(float v, __nv_bfloat16* hi, __nv_bfloat16* lo,
                                         size_t o) {
    __nv_bfloat16 h = __float2bfloat16(v);
    hi[o] = h; lo[o] = __float2bfloat16(v - __bfloat162float(h));
}

// -------- fp32 -> bf16 hi/lo split --------
__global__ __launch_bounds__(256) void conv_split(
    const float* __restrict__ s, __nv_bfloat16* __restrict__ hi,
    __nv_bfloat16* __restrict__ lo, int n4)
{
    int i = blockIdx.x * 256 + threadIdx.x;
    if (i >= n4) return;
    float4 v = ((const float4*)s)[i];
    __nv_bfloat16 a0 = __float2bfloat16(v.x), a1 = __float2bfloat16(v.y);
    __nv_bfloat16 a2 = __float2bfloat16(v.z), a3 = __float2bfloat16(v.w);
    __nv_bfloat162 h0, h1, l0, l1;
    h0.x = a0; h0.y = a1; h1.x = a2; h1.y = a3;
    l0.x = __float2bfloat16(v.x - __bfloat162float(a0));
    l0.y = __float2bfloat16(v.y - __bfloat162float(a1));
    l1.x = __float2bfloat16(v.z - __bfloat162float(a2));
    l1.y = __float2bfloat16(v.w - __bfloat162float(a3));
    ((__nv_bfloat162*)hi)[2*i] = h0; ((__nv_bfloat162*)hi)[2*i+1] = h1;
    ((__nv_bfloat162*)lo)[2*i] = l0; ((__nv_bfloat162*)lo)[2*i+1] = l1;
}

// -------- HMMA bf16x3 GEMM (unchanged from R4) --------
#define AST   18432
#define STG_B (4 * AST)
#define GSMEM (2 * STG_B)

__device__ __forceinline__ void g_load_stage(
    uint32_t sb, const char* pAhi, const char* pAlo,
    const char* pBhi, const char* pBlo, int t, int s)
{
    const size_t gk = (size_t)s * 128;
    #pragma unroll
    for (int j = 0; j < 4; j++) {
        const int c = t + 256 * j;
        const int row = c >> 3, kc = c & 7;
        const size_t go = (size_t)row * 2048 + gk + kc * 16;
        const uint32_t so = row * 144 + kc * 16;
        CP16(sb +          so, pAhi + go);
        CP16(sb +   AST  + so, pAlo + go);
        CP16(sb + 2*AST  + so, pBhi + go);
        CP16(sb + 3*AST  + so, pBlo + go);
    }
    asm volatile("cp.async.commit_group;" ::: "memory");
}

__global__ __launch_bounds__(256) void gemm_hmma3(
    const __nv_bfloat16* __restrict__ Ahi, const __nv_bfloat16* __restrict__ Alo,
    const __nv_bfloat16* __restrict__ Bhi, const __nv_bfloat16* __restrict__ Blo,
    float* __restrict__ C, int ldc)
{
    extern __shared__ char sm[];
    const int t = threadIdx.x, wid = t >> 5, lane = t & 31;
    const int m0 = blockIdx.y * 128, nb = blockIdx.x * 128;
    const uint32_t smb = smem_u32(sm);

    const char* pAhi = (const char*)Ahi + (size_t)m0 * 2048;
    const char* pAlo = (const char*)Alo + (size_t)m0 * 2048;
    const char* pBhi = (const char*)Bhi + (size_t)nb * 2048;
    const char* pBlo = (const char*)Blo + (size_t)nb * 2048;

    const int warp_m = (wid & 1) * 64;
    const int warp_n = (wid >> 1) * 32;
    const int a_m  = lane & 15;
    const int a_kb = lane >> 4;
    const int b_n  = (lane & 7) + ((lane >> 4) & 1) * 8;
    const int b_kb = (lane >> 3) & 1;

    float acc[4][4][4];
    #pragma unroll
    for (int im = 0; im < 4; im++)
        #pragma unroll
        for (int jn = 0; jn < 4; jn++)
            #pragma unroll
            for (int c = 0; c < 4; c++) acc[im][jn][c] = 0.0f;

    g_load_stage(smb,         pAhi, pAlo, pBhi, pBlo, t, 0);
    g_load_stage(smb + STG_B, pAhi, pAlo, pBhi, pBlo, t, 1);

    #pragma unroll 1
    for (int s = 0; s < 16; s++) {
        const int b = s & 1;
        if (s < 15) asm volatile("cp.async.wait_group 1;" ::: "memory");
        else        asm volatile("cp.async.wait_group 0;" ::: "memory");
        __syncthreads();

        const uint32_t sb = smb + b * STG_B;
        #pragma unroll
        for (int kk = 0; kk < 4; kk++) {
            const uint32_t k0 = kk * 16;
            uint32_t ahi[4][4], alo[4][4], bhi[2][4], blo[2][4];
            const uint32_t aoff = (warp_m + a_m) * 144 + (k0 + a_kb * 8) * 2;
            #pragma unroll
            for (int im = 0; im < 4; im++) {
                LDSM4(ahi[im], sb +       aoff + im * (16 * 144));
                LDSM4(alo[im], sb + AST + aoff + im * (16 * 144));
            }
            #pragma unroll
            for (int j2 = 0; j2 < 2; j2++) {
                const uint32_t boff = (warp_n + j2 * 16 + b_n) * 144 + (k0 + b_kb * 8) * 2;
                LDSM4(bhi[j2], sb + 2*AST + boff);
                LDSM4(blo[j2], sb + 3*AST + boff);
            }
            #pragma unroll
            for (int im = 0; im < 4; im++)
                #pragma unroll
                for (int jn = 0; jn < 4; jn++) {
                    const int j2 = jn >> 1, jr = (jn & 1) * 2;
                    MMA16816(acc[im][jn], ahi[im], bhi[j2][jr], bhi[j2][jr + 1]);
                    MMA16816(acc[im][jn], ahi[im], blo[j2][jr], blo[j2][jr + 1]);
                    MMA16816(acc[im][jn], alo[im], bhi[j2][jr], bhi[j2][jr + 1]);
                }
        }
        __syncthreads();
        if (s + 2 < 16) g_load_stage(sb, pAhi, pAlo, pBhi, pBlo, t, s + 2);
    }

    const int r0 = lane >> 2, c0 = (lane & 3) * 2;
    #pragma unroll
    for (int im = 0; im < 4; im++)
        #pragma unroll
        for (int jn = 0; jn < 4; jn++) {
            const int row = m0 + warp_m + im * 16 + r0;
            const int col = nb + warp_n + jn * 8 + c0;
            *(float2*)&C[(size_t)row * ldc + col] =
                make_float2(acc[im][jn][0], acc[im][jn][1]);
            *(float2*)&C[(size_t)(row + 8) * ldc + col] =
                make_float2(acc[im][jn][2], acc[im][jn][3]);
        }
}

// -------- postprocess: V-gate, RMS-norm, rotary, q_gain -> bf16 hi/lo --------
__global__ __launch_bounds__(64) void postproc(const float* __restrict__ q_gain)
{
    const int m = blockIdx.x, unit = blockIdx.y, t = threadIdx.x;
    const float* row = g_qkvg + (size_t)m * NTOT;
    if (unit == 20) {
        #pragma unroll
        for (int i = t; i < 256; i += 64) {
            float v = row[1280 + i], g = row[1536 + i];
            float vg = v / (1.0f + expf(-g));
            int kvh = i >> 6, d = i & 63, hf = d >> 5, dc = d & 31;
            size_t o = ((size_t)(kvh * 2 + hf) * S_LEN + m) * 32 + dc;
            split_bf(vg, g_avh, g_avl, o);
        }
        return;
    }
    const bool isq = unit < 16;
    const int h = isq ? unit : unit - 16;
    const int col0 = isq ? h * HD : 1024 + h * HD;
    float x = row[col0 + t];
    float ss = x * x;
    #pragma unroll
    for (int o = 16; o > 0; o >>= 1) ss += __shfl_xor_sync(0xffffffffu, ss, o);
    __shared__ float s2[2];
    __shared__ float xs[64];
    if ((t & 31) == 0) s2[t >> 5] = ss;
    __syncthreads();
    const float xn = x * rsqrtf((s2[0] + s2[1]) * (1.0f / 64.0f) + 1.1920929e-7f);
    xs[t] = xn;
    __syncthreads();
    if (t < 32) {
        const float x1 = xs[t], x2 = xs[t + 32];
        const float angle = ((float)(2 * t) / 64.0f) * 3.14159274101257324f;
        const float ang = (float)m * angle;
        double a = (double)ang;
        a -= rint(a * 0.15915494309189535) * 6.283185307179586;
        float c, sn;
        sincosf((float)a, &sn, &c);
        const float radius = 1.0f / (1.0f + (float)m * 0.01f);
        c *= radius; sn *= radius;
        float y0 = x1 * c + x2 * sn;
        float y1 = -x1 * sn + x2 * c;
        if (isq) {
            const float gs = q_gain[h] * 0.17677669529663688f;  // fold 1/sqrt(32)
            y0 *= gs; y1 *= gs;
            size_t o0 = ((size_t)(h * 2 + 0) * S_LEN + m) * 32 + t;
            size_t o1 = ((size_t)(h * 2 + 1) * S_LEN + m) * 32 + t;
            split_bf(y0, g_aqh, g_aql, o0);
            split_bf(y1, g_aqh, g_aql, o1);
        } else {
            size_t o0 = ((size_t)(h * 2 + 0) * S_LEN + m) * 32 + t;
            size_t o1 = ((size_t)(h * 2 + 1) * S_LEN + m) * 32 + t;
            split_bf(y0, g_akh, g_akl, o0);
            split_bf(y1, g_akh, g_akl, o1);
        }
    }
}

// -------- HMMA flash attention --------
// block: 64 q-rows of one (head, half). 4 warps x m16. 64-key tiles, dbuf cp.async.
// smem tile: [64 rows][80B] (32 bf16 + pad, conflict-free ldmatrix).
#define ATILE 5120                 // 64 * 80
#define AKV   (4 * ATILE)          // khi,klo,vhi,vlo
#define ASMEM (2 * AKV + 2 * ATILE) // 51200

__device__ __forceinline__ void a_load_kv(
    uint32_t sb, const char* kh, const char* kl,
    const char* vh, const char* vl, int t, int key0)
{
    const char* base[4] = { kh, kl, vh, vl };
    #pragma unroll
    for (int j = 0; j < 8; j++) {
        const int c = t + 128 * j;
        const int arr = c >> 8, rem = c & 255;
        const int row = rem >> 2, c4 = rem & 3;
        CP16(sb + arr * ATILE + row * 80 + c4 * 16,
             base[arr] + ((size_t)(key0 + row) * 32 + c4 * 8) * 2);
    }
    asm volatile("cp.async.commit_group;" ::: "memory");
}

__global__ __launch_bounds__(128) void attn_mma()
{
    extern __shared__ char sm[];
    const int qt = gridDim.x - 1 - blockIdx.x;     // big q-tiles first
    const int h = blockIdx.y, half = blockIdx.z, kvh = h >> 2;
    const int t = threadIdx.x, w = t >> 5, l = t & 31;
    const int q0 = qt * 64;
    const uint32_t smb = smem_u32(sm);
    const uint32_t sQh = smb + 2 * AKV, sQl = sQh + ATILE;

    const char* qh_g = (const char*)(g_aqh + ((size_t)(h * 2 + half) * S_LEN + q0) * 32);
    const char* ql_g = (const char*)(g_aql + ((size_t)(h * 2 + half) * S_LEN + q0) * 32);
    const char* kh_g = (const char*)(g_akh + (size_t)(kvh * 2 + half) * S_LEN * 32);
    const char* kl_g = (const char*)(g_akl + (size_t)(kvh * 2 + half) * S_LEN * 32);
    const char* vh_g = (const char*)(g_avh + (size_t)(kvh * 2 + half) * S_LEN * 32);
    const char* vl_g = (const char*)(g_avl + (size_t)(kvh * 2 + half) * S_LEN * 32);

    // group 0: Q (both hi/lo) + KV tile 0
    #pragma unroll
    for (int j = 0; j < 4; j++) {
        const int c = t + 128 * j;
        const int arr = c >> 8, rem = c & 255;
        const int row = rem >> 2, c4 = rem & 3;
        CP16((arr ? sQl : sQh) + row * 80 + c4 * 16,
             (arr ? ql_g : qh_g) + ((size_t)row * 32 + c4 * 8) * 2);
    }
    a_load_kv(smb, kh_g, kl_g, vh_g, vl_g, t, 0);
    const int nt = qt + 1;
    if (nt > 1) a_load_kv(smb + AKV, kh_g, kl_g, vh_g, vl_g, t, 64);

    uint32_t qh[2][4], ql[2][4];
    float O[4][4];
    #pragma unroll
    for (int nd = 0; nd < 4; nd++)
        #pragma unroll
        for (int c = 0; c < 4; c++) O[nd][c] = 0.0f;
    float m0 = -1e30f, m1 = -1e30f, lp0 = 0.0f, lp1 = 0.0f;

    const int row0 = q0 + w * 16 + (l >> 2);

    #pragma unroll 1
    for (int i = 0; i < nt; i++) {
        if (i + 1 < nt) asm volatile("cp.async.wait_group 1;" ::: "memory");
        else            asm volatile("cp.async.wait_group 0;" ::: "memory");
        __syncthreads();

        if (i == 0) {
            const uint32_t qoff = (w * 16 + (l & 15)) * 80 + ((l >> 4) * 8) * 2;
            LDSM4(qh[0], sQh + qoff);       LDSM4(qh[1], sQh + qoff + 32);
            LDSM4(ql[0], sQl + qoff);       LDSM4(ql[1], sQl + qoff + 32);
        }

        const uint32_t sb = smb + (i & 1) * AKV;
        const int key0 = i * 64;

        // ---- QK^T: s[8 ntiles][4] ----
        float s[8][4];
        #pragma unroll
        for (int n = 0; n < 8; n++)
            #pragma unroll
            for (int c = 0; c < 4; c++) s[n][c] = 0.0f;

        #pragma unroll
        for (int ks = 0; ks < 2; ks++) {
            #pragma unroll
            for (int g = 0; g < 4; g++) {
                uint32_t kh[4], kl[4];
                const uint32_t ka = sb
                    + (g * 16 + (l & 7) + ((l >> 4) & 1) * 8) * 80
                    + (ks * 16 + ((l >> 3) & 1) * 8) * 2;
                LDSM4(kh, ka);
                LDSM4(kl, ka + ATILE);
                MMA16816(s[2*g],   qh[ks], kh[0], kh[1]);
                MMA16816(s[2*g],   qh[ks], kl[0], kl[1]);
                MMA16816(s[2*g],   ql[ks], kh[0], kh[1]);
                MMA16816(s[2*g+1], qh[ks], kh[2], kh[3]);
                MMA16816(s[2*g+1], qh[ks], kl[2], kl[3]);
                MMA16816(s[2*g+1], ql[ks], kh[2], kh[3]);
            }
        }

        // ---- causal mask (diagonal tile only) ----
        if (i == nt - 1) {
            #pragma unroll
            for (int n = 0; n < 8; n++) {
                const int cb = key0 + n * 8 + (l & 3) * 2;
                if (cb     > row0)     s[n][0] = -1e30f;
                if (cb + 1 > row0)     s[n][1] = -1e30f;
                if (cb     > row0 + 8) s[n][2] = -1e30f;
                if (cb + 1 > row0 + 8) s[n][3] = -1e30f;
            }
        }

        // ---- online softmax ----
        float mt0 = -1e30f, mt1 = -1e30f;
        #pragma unroll
        for (int n = 0; n < 8; n++) {
            mt0 = fmaxf(mt0, fmaxf(s[n][0], s[n][1]));
            mt1 = fmaxf(mt1, fmaxf(s[n][2], s[n][3]));
        }
        mt0 = fmaxf(mt0, __shfl_xor_sync(0xffffffffu, mt0, 1));
        mt0 = fmaxf(mt0, __shfl_xor_sync(0xffffffffu, mt0, 2));
        mt1 = fmaxf(mt1, __shfl_xor_sync(0xffffffffu, mt1, 1));
        mt1 = fmaxf(mt1, __shfl_xor_sync(0xffffffffu, mt1, 2));
        const float mn0 = fmaxf(m0, mt0), mn1 = fmaxf(m1, mt1);
        const float cr0 = __expf(m0 - mn0), cr1 = __expf(m1 - mn1);
        m0 = mn0; m1 = mn1;
        lp0 *= cr0; lp1 *= cr1;
        #pragma unroll
        for (int nd = 0; nd < 4; nd++) {
            O[nd][0] *= cr0; O[nd][1] *= cr0;
            O[nd][2] *= cr1; O[nd][3] *= cr1;
        }

        // ---- exp + pack P hi/lo as A-fragments ----
        uint32_t aPh[4][4], aPl[4][4];
        #pragma unroll
        for (int j = 0; j < 4; j++) {
            #pragma unroll
            for (int q = 0; q < 2; q++) {          // ntile 2j+q -> regs 2q,2q+1
                const int n = 2 * j + q;
                float p0 = __expf(s[n][0] - mn0);
                float p1 = __expf(s[n][1] - mn0);
                float p2 = __expf(s[n][2] - mn1);
                float p3 = __expf(s[n][3] - mn1);
                lp0 += p0 + p1; lp1 += p2 + p3;
                uint32_t h01, h23;
                PACKBF(h01, p0, p1);
                PACKBF(h23, p2, p3);
                aPh[j][2*q]   = h01;
                aPh[j][2*q+1] = h23;
                float f0 = __uint_as_float(h01 << 16);
                float f1 = __uint_as_float(h01 & 0xffff0000u);
                float f2 = __uint_as_float(h23 << 16);
                float f3 = __uint_as_float(h23 & 0xffff0000u);
                uint32_t l01, l23;
                PACKBF(l01, p0 - f0, p1 - f1);
                PACKBF(l23, p2 - f2, p3 - f3);
                aPl[j][2*q]   = l01;
                aPl[j][2*q+1] = l23;
            }
        }

        // ---- P @ V ----
        #pragma unroll
        for (int j = 0; j < 4; j++) {
            #pragma unroll
            for (int dg = 0; dg < 2; dg++) {
                uint32_t vh[4], vl[4];
                const uint32_t va = sb + 2 * ATILE
                    + (16 * j + (l & 7) + ((l >> 3) & 1) * 8) * 80
                    + (dg * 16 + ((l >> 4) & 1) * 8) * 2;
                LDSM4T(vh, va);
                LDSM4T(vl, va + ATILE);
                MMA16816(O[2*dg],   aPh[j], vh[0], vh[1]);
                MMA16816(O[2*dg],   aPh[j], vl[0], vl[1]);
                MMA16816(O[2*dg],   aPl[j], vh[0], vh[1]);
                MMA16816(O[2*dg+1], aPh[j], vh[2], vh[3]);
                MMA16816(O[2*dg+1], aPh[j], vl[2], vl[3]);
                MMA16816(O[2*dg+1], aPl[j], vh[2], vh[3]);
            }
        }

        __syncthreads();
        if (i + 2 < nt)
            a_load_kv(sb, kh_g, kl_g, vh_g, vl_g, t, (i + 2) * 64);
    }

    lp0 += __shfl_xor_sync(0xffffffffu, lp0, 1);
    lp0 += __shfl_xor_sync(0xffffffffu, lp0, 2);
    lp1 += __shfl_xor_sync(0xffffffffu, lp1, 1);
    lp1 += __shfl_xor_sync(0xffffffffu, lp1, 2);
    const float inv0 = 1.0f / lp0, inv1 = 1.0f / lp1;

    #pragma unroll
    for (int nd = 0; nd < 4; nd++) {
        const int col = half * 32 + nd * 8 + (l & 3) * 2;
        *(float2*)&g_a[((size_t)h * S_LEN + row0) * HD + col] =
            make_float2(O[nd][0] * inv0, O[nd][1] * inv0);
        *(float2*)&g_a[((size_t)h * S_LEN + row0 + 8) * HD + col] =
            make_float2(O[nd][2] * inv1, O[nd][3] * inv1);
    }
}

// -------- differential combine -> bf16 hi/lo --------
__global__ __launch_bounds__(512) void combine2(const float* __restrict__ lambda_p)
{
    const int m = blockIdx.x, t = threadIdx.x;
    const int h = t >> 5, j = t & 31;
    const float lam = lambda_p[h];
    const float* ap = g_a + ((size_t)h * S_LEN + m) * HD;
    const float a1 = ap[j], a2 = ap[j + 32];
    const float y1 = a1 - lam * a2, y2 = a1 + lam * a2;
    const size_t o1 = (size_t)m * DIM + h * HD + j, o2 = o1 + 32;
    split_bf(y1, g_yhi, g_ylo, o1);
    split_bf(y2, g_yhi, g_ylo, o2);
}

extern "C" void kernel_launch(void* const* d_in, const int* in_sizes, int n_in,
                              void* d_out, int out_size)
{
    const float* x        = (const float*)d_in[0];
    const float* Wq       = (const float*)d_in[1];
    const float* Wk       = (const float*)d_in[2];
    const float* Wv       = (const float*)d_in[3];
    const float* Wg       = (const float*)d_in[4];
    const float* Wo       = (const float*)d_in[5];
    const float* q_gain   = (const float*)d_in[6];
    const float* lambda_p = (const float*)d_in[7];
    float* out = (float*)d_out;

    cudaFuncSetAttribute(gemm_hmma3, cudaFuncAttributeMaxDynamicSharedMemorySize, GSMEM);
    cudaFuncSetAttribute(attn_mma, cudaFuncAttributeMaxDynamicSharedMemorySize, ASMEM);

    float* qkvg_p;
    __nv_bfloat16 *xhi, *xlo, *whi, *wlo, *wohi, *wolo, *yhi, *ylo;
    cudaGetSymbolAddress((void**)&qkvg_p, g_qkvg);
    cudaGetSymbolAddress((void**)&xhi, g_xhi);   cudaGetSymbolAddress((void**)&xlo, g_xlo);
    cudaGetSymbolAddress((void**)&whi, g_whi);   cudaGetSymbolAddress((void**)&wlo, g_wlo);
    cudaGetSymbolAddress((void**)&wohi, g_wohi); cudaGetSymbolAddress((void**)&wolo, g_wolo);
    cudaGetSymbolAddress((void**)&yhi, g_yhi);   cudaGetSymbolAddress((void**)&ylo, g_ylo);

    conv_split<<<2048, 256>>>(x,  xhi, xlo, 524288);
    conv_split<<<1024, 256>>>(Wq, whi, wlo, 262144);
    conv_split<<<256,  256>>>(Wk, whi + 1024*1024, wlo + 1024*1024, 65536);
    conv_split<<<256,  256>>>(Wv, whi + 1280*1024, wlo + 1280*1024, 65536);
    conv_split<<<256,  256>>>(Wg, whi + 1536*1024, wlo + 1536*1024, 65536);
    conv_split<<<1024, 256>>>(Wo, wohi, wolo, 262144);

    gemm_hmma3<<<dim3(NTOT/128, S_LEN/128), 256, GSMEM>>>(xhi, xlo, whi, wlo, qkvg_p, NTOT);
    postproc<<<dim3(S_LEN, 21), 64>>>(q_gain);
    attn_mma<<<dim3(S_LEN/64, NH, 2), 128, ASMEM>>>();
    combine2<<<S_LEN, 512>>>(lambda_p);
    gemm_hmma3<<<dim3(DIM/128, S_LEN/128), 256, GSMEM>>>(yhi, ylo, wohi, wolo, out, DIM);
}

// round 6
// speedup vs baseline: 5.3707x; 1.0693x over previous
#include <cuda_runtime.h>
#include <cuda_bf16.h>
#include <math.h>
#include <stdint.h>

#define S_LEN 2048
#define DIM 1024
#define NH 16
#define KVH 4
#define HD 64
#define NTOT 1792

__device__ float g_qkvg[S_LEN * NTOT];
__device__ float g_a[NH * S_LEN * HD];
__device__ float2 g_rot[S_LEN * 32];
__device__ __nv_bfloat16 g_xhi[S_LEN * DIM],  g_xlo[S_LEN * DIM];
__device__ __nv_bfloat16 g_whi[NTOT * DIM],   g_wlo[NTOT * DIM];
__device__ __nv_bfloat16 g_wohi[DIM * DIM],   g_wolo[DIM * DIM];
__device__ __nv_bfloat16 g_yhi[S_LEN * DIM],  g_ylo[S_LEN * DIM];
// attention operands, bf16 hi/lo, layout [(head*2+half)][seq][32]
__device__ __nv_bfloat16 g_aqh[NH*2*S_LEN*32], g_aql[NH*2*S_LEN*32];
__device__ __nv_bfloat16 g_akh[KVH*2*S_LEN*32], g_akl[KVH*2*S_LEN*32];
__device__ __nv_bfloat16 g_avh[KVH*2*S_LEN*32], g_avl[KVH*2*S_LEN*32];

__device__ __forceinline__ uint32_t smem_u32(const void* p) {
    uint32_t a;
    asm("{ .reg .u64 t; cvta.to.shared.u64 t, %1; cvt.u32.u64 %0, t; }" : "=r"(a) : "l"(p));
    return a;
}
#define CP16(sm, gp) asm volatile("cp.async.cg.shared.global [%0], [%1], 16;" :: "r"(sm), "l"(gp))
#define LDSM4(r, addr) \
    asm volatile("ldmatrix.sync.aligned.m8n8.x4.shared.b16 {%0,%1,%2,%3}, [%4];" \
        : "=r"((r)[0]), "=r"((r)[1]), "=r"((r)[2]), "=r"((r)[3]) : "r"(addr))
#define LDSM4T(r, addr) \
    asm volatile("ldmatrix.sync.aligned.m8n8.x4.trans.shared.b16 {%0,%1,%2,%3}, [%4];" \
        : "=r"((r)[0]), "=r"((r)[1]), "=r"((r)[2]), "=r"((r)[3]) : "r"(addr))
#define MMA16816(d, a, b0, b1) \
    asm volatile("mma.sync.aligned.m16n8k16.row.col.f32.bf16.bf16.f32 " \
        "{%0,%1,%2,%3}, {%4,%5,%6,%7}, {%8,%9}, {%0,%1,%2,%3};" \
        : "+f"((d)[0]), "+f"((d)[1]), "+f"((d)[2]), "+f"((d)[3]) \
        : "r"((a)[0]), "r"((a)[1]), "r"((a)[2]), "r"((a)[3]), "r"(b0), "r"(b1))
#define PACKBF(r, a, b) asm("cvt.rn.bf16x2.f32 %0, %1, %2;" : "=r"(r) : "f"(b), "f"(a))
#define EX2(d, x) asm("ex2.approx.ftz.f32 %0, %1;" : "=f"(d) : "f"(x))

__device__ __forceinline__ void split_bf(float v, __nv_bfloat16* hi, __nv_bfloat16* lo,
                                         size_t o) {
    __nv_bfloat16 h = __float2bfloat16(v);
    hi[o] = h; lo[o] = __float2bfloat16(v - __bfloat162float(h));
}

// -------- fused fp32 -> bf16 hi/lo split for all 6 tensors --------
__global__ __launch_bounds__(256) void conv_all(
    const float* __restrict__ x,  const float* __restrict__ Wq,
    const float* __restrict__ Wk, const float* __restrict__ Wv,
    const float* __restrict__ Wg, const float* __restrict__ Wo)
{
    const int i = blockIdx.x * 256 + threadIdx.x;   // float4 index, < 1245184
    const float* s; __nv_bfloat16 *hi, *lo;
    if (i < 524288)      { size_t j = (size_t)i * 4;            s = x  + j; hi = g_xhi + j;            lo = g_xlo + j; }
    else if (i < 786432) { size_t j = (size_t)(i - 524288) * 4; s = Wq + j; hi = g_whi + j;            lo = g_wlo + j; }
    else if (i < 851968) { size_t j = (size_t)(i - 786432) * 4; s = Wk + j; hi = g_whi + 1048576 + j;  lo = g_wlo + 1048576 + j; }
    else if (i < 917504) { size_t j = (size_t)(i - 851968) * 4; s = Wv + j; hi = g_whi + 1310720 + j;  lo = g_wlo + 1310720 + j; }
    else if (i < 983040) { size_t j = (size_t)(i - 917504) * 4; s = Wg + j; hi = g_whi + 1572864 + j;  lo = g_wlo + 1572864 + j; }
    else                 { size_t j = (size_t)(i - 983040) * 4; s = Wo + j; hi = g_wohi + j;           lo = g_wolo + j; }
    float4 v = *(const float4*)s;
    __nv_bfloat16 a0 = __float2bfloat16(v.x), a1 = __float2bfloat16(v.y);
    __nv_bfloat16 a2 = __float2bfloat16(v.z), a3 = __float2bfloat16(v.w);
    __nv_bfloat162 h0, h1, l0, l1;
    h0.x = a0; h0.y = a1; h1.x = a2; h1.y = a3;
    l0.x = __float2bfloat16(v.x - __bfloat162float(a0));
    l0.y = __float2bfloat16(v.y - __bfloat162float(a1));
    l1.x = __float2bfloat16(v.z - __bfloat162float(a2));
    l1.y = __float2bfloat16(v.w - __bfloat162float(a3));
    *(__nv_bfloat162*)hi = h0; *(__nv_bfloat162*)(hi + 2) = h1;
    *(__nv_bfloat162*)lo = l0; *(__nv_bfloat162*)(lo + 2) = l1;
}

// -------- rotary table: g_rot[m][t] = radius * (cos, sin) --------
__global__ __launch_bounds__(256) void rotab()
{
    const int i = blockIdx.x * 256 + threadIdx.x;   // < 65536
    const int m = i >> 5, t = i & 31;
    const float angle = ((float)(2 * t) / 64.0f) * 3.14159274101257324f;
    const float ang = (float)m * angle;
    double a = (double)ang;
    a -= rint(a * 0.15915494309189535) * 6.283185307179586;
    float c, sn;
    sincosf((float)a, &sn, &c);
    const float radius = 1.0f / (1.0f + (float)m * 0.01f);
    g_rot[i] = make_float2(c * radius, sn * radius);
}

// -------- HMMA bf16x3 GEMM (unchanged) --------
#define AST   18432
#define STG_B (4 * AST)
#define GSMEM (2 * STG_B)

__device__ __forceinline__ void g_load_stage(
    uint32_t sb, const char* pAhi, const char* pAlo,
    const char* pBhi, const char* pBlo, int t, int s)
{
    const size_t gk = (size_t)s * 128;
    #pragma unroll
    for (int j = 0; j < 4; j++) {
        const int c = t + 256 * j;
        const int row = c >> 3, kc = c & 7;
        const size_t go = (size_t)row * 2048 + gk + kc * 16;
        const uint32_t so = row * 144 + kc * 16;
        CP16(sb +          so, pAhi + go);
        CP16(sb +   AST  + so, pAlo + go);
        CP16(sb + 2*AST  + so, pBhi + go);
        CP16(sb + 3*AST  + so, pBlo + go);
    }
    asm volatile("cp.async.commit_group;" ::: "memory");
}

__global__ __launch_bounds__(256) void gemm_hmma3(
    const __nv_bfloat16* __restrict__ Ahi, const __nv_bfloat16* __restrict__ Alo,
    const __nv_bfloat16* __restrict__ Bhi, const __nv_bfloat16* __restrict__ Blo,
    float* __restrict__ C, int ldc)
{
    extern __shared__ char sm[];
    const int t = threadIdx.x, wid = t >> 5, lane = t & 31;
    const int m0 = blockIdx.y * 128, nb = blockIdx.x * 128;
    const uint32_t smb = smem_u32(sm);

    const char* pAhi = (const char*)Ahi + (size_t)m0 * 2048;
    const char* pAlo = (const char*)Alo + (size_t)m0 * 2048;
    const char* pBhi = (const char*)Bhi + (size_t)nb * 2048;
    const char* pBlo = (const char*)Blo + (size_t)nb * 2048;

    const int warp_m = (wid & 1) * 64;
    const int warp_n = (wid >> 1) * 32;
    const int a_m  = lane & 15;
    const int a_kb = lane >> 4;
    const int b_n  = (lane & 7) + ((lane >> 4) & 1) * 8;
    const int b_kb = (lane >> 3) & 1;

    float acc[4][4][4];
    #pragma unroll
    for (int im = 0; im < 4; im++)
        #pragma unroll
        for (int jn = 0; jn < 4; jn++)
            #pragma unroll
            for (int c = 0; c < 4; c++) acc[im][jn][c] = 0.0f;

    g_load_stage(smb,         pAhi, pAlo, pBhi, pBlo, t, 0);
    g_load_stage(smb + STG_B, pAhi, pAlo, pBhi, pBlo, t, 1);

    #pragma unroll 1
    for (int s = 0; s < 16; s++) {
        const int b = s & 1;
        if (s < 15) asm volatile("cp.async.wait_group 1;" ::: "memory");
        else        asm volatile("cp.async.wait_group 0;" ::: "memory");
        __syncthreads();

        const uint32_t sb = smb + b * STG_B;
        #pragma unroll
        for (int kk = 0; kk < 4; kk++) {
            const uint32_t k0 = kk * 16;
            uint32_t ahi[4][4], alo[4][4], bhi[2][4], blo[2][4];
            const uint32_t aoff = (warp_m + a_m) * 144 + (k0 + a_kb * 8) * 2;
            #pragma unroll
            for (int im = 0; im < 4; im++) {
                LDSM4(ahi[im], sb +       aoff + im * (16 * 144));
                LDSM4(alo[im], sb + AST + aoff + im * (16 * 144));
            }
            #pragma unroll
            for (int j2 = 0; j2 < 2; j2++) {
                const uint32_t boff = (warp_n + j2 * 16 + b_n) * 144 + (k0 + b_kb * 8) * 2;
                LDSM4(bhi[j2], sb + 2*AST + boff);
                LDSM4(blo[j2], sb + 3*AST + boff);
            }
            #pragma unroll
            for (int im = 0; im < 4; im++)
                #pragma unroll
                for (int jn = 0; jn < 4; jn++) {
                    const int j2 = jn >> 1, jr = (jn & 1) * 2;
                    MMA16816(acc[im][jn], ahi[im], bhi[j2][jr], bhi[j2][jr + 1]);
                    MMA16816(acc[im][jn], ahi[im], blo[j2][jr], blo[j2][jr + 1]);
                    MMA16816(acc[im][jn], alo[im], bhi[j2][jr], bhi[j2][jr + 1]);
                }
        }
        __syncthreads();
        if (s + 2 < 16) g_load_stage(sb, pAhi, pAlo, pBhi, pBlo, t, s + 2);
    }

    const int r0 = lane >> 2, c0 = (lane & 3) * 2;
    #pragma unroll
    for (int im = 0; im < 4; im++)
        #pragma unroll
        for (int jn = 0; jn < 4; jn++) {
            const int row = m0 + warp_m + im * 16 + r0;
            const int col = nb + warp_n + jn * 8 + c0;
            *(float2*)&C[(size_t)row * ldc + col] =
                make_float2(acc[im][jn][0], acc[im][jn][1]);
            *(float2*)&C[(size_t)(row + 8) * ldc + col] =
                make_float2(acc[im][jn][2], acc[im][jn][3]);
        }
}

// -------- postprocess: warp-per-unit, no smem --------
// grid (S, 3), block 256 = 8 warps; unit = by*8 + warp; 0-15 q, 16-19 k, 20 vgate.
#define LOG2E 1.4426950408889634f
__global__ __launch_bounds__(256) void postproc(const float* __restrict__ q_gain)
{
    const int m = blockIdx.x;
    const int w = threadIdx.x >> 5, l = threadIdx.x & 31;
    const int unit = blockIdx.y * 8 + w;
    if (unit >= 21) return;
    const float* row = g_qkvg + (size_t)m * NTOT;

    if (unit == 20) {
        #pragma unroll
        for (int i = l; i < 256; i += 32) {
            float v = row[1280 + i], g = row[1536 + i];
            float vg = v / (1.0f + __expf(-g));
            int kvh = i >> 6, d = i & 63, hf = d >> 5, dc = d & 31;
            size_t o = ((size_t)(kvh * 2 + hf) * S_LEN + m) * 32 + dc;
            split_bf(vg, g_avh, g_avl, o);
        }
        return;
    }
    const bool isq = unit < 16;
    const int h = isq ? unit : unit - 16;
    const int col0 = isq ? h * HD : 1024 + h * HD;
    float x1 = row[col0 + l], x2 = row[col0 + l + 32];
    float ss = x1 * x1 + x2 * x2;
    #pragma unroll
    for (int o = 16; o > 0; o >>= 1) ss += __shfl_xor_sync(0xffffffffu, ss, o);
    const float rn = rsqrtf(ss * (1.0f / 64.0f) + 1.1920929e-7f);
    x1 *= rn; x2 *= rn;
    const float2 rc = g_rot[m * 32 + l];
    float y0 = x1 * rc.x + x2 * rc.y;
    float y1 = -x1 * rc.y + x2 * rc.x;
    const size_t o0 = ((size_t)(h * 2 + 0) * S_LEN + m) * 32 + l;
    const size_t o1 = ((size_t)(h * 2 + 1) * S_LEN + m) * 32 + l;
    if (isq) {
        const float gs = q_gain[h] * (0.17677669529663688f * LOG2E); // fold scale+log2e
        y0 *= gs; y1 *= gs;
        split_bf(y0, g_aqh, g_aql, o0);
        split_bf(y1, g_aqh, g_aql, o1);
    } else {
        split_bf(y0, g_akh, g_akl, o0);
        split_bf(y1, g_akh, g_akl, o1);
    }
}

// -------- HMMA flash attention: 128 q-rows, 8 warps, exp2 softmax --------
#define ATILE 5120                     // 64 rows * 80B
#define QTILE 10240                    // 128 rows * 80B
#define AKV   (4 * ATILE)
#define ASMEM (2 * AKV + 2 * QTILE)    // 61440

__device__ __forceinline__ void a_load_kv(
    uint32_t sb, const char* kh, const char* kl,
    const char* vh, const char* vl, int t, int key0)
{
    const char* base[4] = { kh, kl, vh, vl };
    #pragma unroll
    for (int j = 0; j < 4; j++) {
        const int c = t + 256 * j;
        const int arr = c >> 8, rem = c & 255;
        const int row = rem >> 2, c4 = rem & 3;
        CP16(sb + arr * ATILE + row * 80 + c4 * 16,
             base[arr] + ((size_t)(key0 + row) * 32 + c4 * 8) * 2);
    }
    asm volatile("cp.async.commit_group;" ::: "memory");
}

__global__ __launch_bounds__(256) void attn_mma()
{
    extern __shared__ char sm[];
    const int qt = gridDim.x - 1 - blockIdx.x;     // big q-tiles first
    const int h = blockIdx.y, half = blockIdx.z, kvh = h >> 2;
    const int t = threadIdx.x, w = t >> 5, l = t & 31;
    const int q0 = qt * 128;
    const uint32_t smb = smem_u32(sm);
    const uint32_t sQh = smb + 2 * AKV, sQl = sQh + QTILE;

    const char* qh_g = (const char*)(g_aqh + ((size_t)(h * 2 + half) * S_LEN + q0) * 32);
    const char* ql_g = (const char*)(g_aql + ((size_t)(h * 2 + half) * S_LEN + q0) * 32);
    const char* kh_g = (const char*)(g_akh + (size_t)(kvh * 2 + half) * S_LEN * 32);
    const char* kl_g = (const char*)(g_akl + (size_t)(kvh * 2 + half) * S_LEN * 32);
    const char* vh_g = (const char*)(g_avh + (size_t)(kvh * 2 + half) * S_LEN * 32);
    const char* vl_g = (const char*)(g_avl + (size_t)(kvh * 2 + half) * S_LEN * 32);

    // group 0: Q (hi/lo, 128 rows) + KV tile 0
    #pragma unroll
    for (int j = 0; j < 4; j++) {
        const int c = t + 256 * j;
        const int arr = c >> 9, rem = c & 511;
        const int row = rem >> 2, c4 = rem & 3;
        CP16((arr ? sQl : sQh) + row * 80 + c4 * 16,
             (arr ? ql_g : qh_g) + ((size_t)row * 32 + c4 * 8) * 2);
    }
    a_load_kv(smb, kh_g, kl_g, vh_g, vl_g, t, 0);
    const int nt = 2 * qt + 2;
    if (nt > 1) a_load_kv(smb + AKV, kh_g, kl_g, vh_g, vl_g, t, 64);

    uint32_t qh[2][4], ql[2][4];
    float O[4][4];
    #pragma unroll
    for (int nd = 0; nd < 4; nd++)
        #pragma unroll
        for (int c = 0; c < 4; c++) O[nd][c] = 0.0f;
    float m0 = -1e30f, m1 = -1e30f, lp0 = 0.0f, lp1 = 0.0f;

    const int row0 = q0 + w * 16 + (l >> 2);
    const int qmax_w = q0 + w * 16 + 15;
    const int qmin_w = q0 + w * 16;

    #pragma unroll 1
    for (int i = 0; i < nt; i++) {
        if (i + 1 < nt) asm volatile("cp.async.wait_group 1;" ::: "memory");
        else            asm volatile("cp.async.wait_group 0;" ::: "memory");
        __syncthreads();

        if (i == 0) {
            const uint32_t qoff = (w * 16 + (l & 15)) * 80 + ((l >> 4) * 8) * 2;
            LDSM4(qh[0], sQh + qoff);       LDSM4(qh[1], sQh + qoff + 32);
            LDSM4(ql[0], sQl + qoff);       LDSM4(ql[1], sQl + qoff + 32);
        }

        const uint32_t sb = smb + (i & 1) * AKV;
        const int key0 = i * 64;

        if (key0 <= qmax_w) {                       // skip fully-masked tiles
            float s[8][4];
            #pragma unroll
            for (int n = 0; n < 8; n++)
                #pragma unroll
                for (int c = 0; c < 4; c++) s[n][c] = 0.0f;

            #pragma unroll
            for (int ks = 0; ks < 2; ks++) {
                #pragma unroll
                for (int g = 0; g < 4; g++) {
                    uint32_t kh[4], kl[4];
                    const uint32_t ka = sb
                        + (g * 16 + (l & 7) + ((l >> 4) & 1) * 8) * 80
                        + (ks * 16 + ((l >> 3) & 1) * 8) * 2;
                    LDSM4(kh, ka);
                    LDSM4(kl, ka + ATILE);
                    MMA16816(s[2*g],   qh[ks], kh[0], kh[1]);
                    MMA16816(s[2*g],   qh[ks], kl[0], kl[1]);
                    MMA16816(s[2*g],   ql[ks], kh[0], kh[1]);
                    MMA16816(s[2*g+1], qh[ks], kh[2], kh[3]);
                    MMA16816(s[2*g+1], qh[ks], kl[2], kl[3]);
                    MMA16816(s[2*g+1], ql[ks], kh[2], kh[3]);
                }
            }

            if (key0 + 63 > qmin_w) {               // diagonal tile(s): mask
                #pragma unroll
                for (int n = 0; n < 8; n++) {
                    const int cb = key0 + n * 8 + (l & 3) * 2;
                    if (cb     > row0)     s[n][0] = -1e30f;
                    if (cb + 1 > row0)     s[n][1] = -1e30f;
                    if (cb     > row0 + 8) s[n][2] = -1e30f;
                    if (cb + 1 > row0 + 8) s[n][3] = -1e30f;
                }
            }

            float mt0 = -1e30f, mt1 = -1e30f;
            #pragma unroll
            for (int n = 0; n < 8; n++) {
                mt0 = fmaxf(mt0, fmaxf(s[n][0], s[n][1]));
                mt1 = fmaxf(mt1, fmaxf(s[n][2], s[n][3]));
            }
            mt0 = fmaxf(mt0, __shfl_xor_sync(0xffffffffu, mt0, 1));
            mt0 = fmaxf(mt0, __shfl_xor_sync(0xffffffffu, mt0, 2));
            mt1 = fmaxf(mt1, __shfl_xor_sync(0xffffffffu, mt1, 1));
            mt1 = fmaxf(mt1, __shfl_xor_sync(0xffffffffu, mt1, 2));
            const float mn0 = fmaxf(m0, mt0), mn1 = fmaxf(m1, mt1);
            float cr0, cr1;
            EX2(cr0, m0 - mn0); EX2(cr1, m1 - mn1);
            m0 = mn0; m1 = mn1;
            lp0 *= cr0; lp1 *= cr1;
            #pragma unroll
            for (int nd = 0; nd < 4; nd++) {
                O[nd][0] *= cr0; O[nd][1] *= cr0;
                O[nd][2] *= cr1; O[nd][3] *= cr1;
            }

            uint32_t aPh[4][4], aPl[4][4];
            #pragma unroll
            for (int j = 0; j < 4; j++) {
                #pragma unroll
                for (int q = 0; q < 2; q++) {
                    const int n = 2 * j + q;
                    float p0, p1, p2, p3;
                    EX2(p0, s[n][0] - mn0);
                    EX2(p1, s[n][1] - mn0);
                    EX2(p2, s[n][2] - mn1);
                    EX2(p3, s[n][3] - mn1);
                    lp0 += p0 + p1; lp1 += p2 + p3;
                    uint32_t h01, h23;
                    PACKBF(h01, p0, p1);
                    PACKBF(h23, p2, p3);
                    aPh[j][2*q]   = h01;
                    aPh[j][2*q+1] = h23;
                    float f0 = __uint_as_float(h01 << 16);
                    float f1 = __uint_as_float(h01 & 0xffff0000u);
                    float f2 = __uint_as_float(h23 << 16);
                    float f3 = __uint_as_float(h23 & 0xffff0000u);
                    uint32_t l01, l23;
                    PACKBF(l01, p0 - f0, p1 - f1);
                    PACKBF(l23, p2 - f2, p3 - f3);
                    aPl[j][2*q]   = l01;
                    aPl[j][2*q+1] = l23;
                }
            }

            #pragma unroll
            for (int j = 0; j < 4; j++) {
                #pragma unroll
                for (int dg = 0; dg < 2; dg++) {
                    uint32_t vh[4], vl[4];
                    const uint32_t va = sb + 2 * ATILE
                        + (16 * j + (l & 7) + ((l >> 3) & 1) * 8) * 80
                        + (dg * 16 + ((l >> 4) & 1) * 8) * 2;
                    LDSM4T(vh, va);
                    LDSM4T(vl, va + ATILE);
                    MMA16816(O[2*dg],   aPh[j], vh[0], vh[1]);
                    MMA16816(O[2*dg],   aPh[j], vl[0], vl[1]);
                    MMA16816(O[2*dg],   aPl[j], vh[0], vh[1]);
                    MMA16816(O[2*dg+1], aPh[j], vh[2], vh[3]);
                    MMA16816(O[2*dg+1], aPh[j], vl[2], vl[3]);
                    MMA16816(O[2*dg+1], aPl[j], vh[2], vh[3]);
                }
            }
        }

        __syncthreads();
        if (i + 2 < nt)
            a_load_kv(sb, kh_g, kl_g, vh_g, vl_g, t, (i + 2) * 64);
    }

    lp0 += __shfl_xor_sync(0xffffffffu, lp0, 1);
    lp0 += __shfl_xor_sync(0xffffffffu, lp0, 2);
    lp1 += __shfl_xor_sync(0xffffffffu, lp1, 1);
    lp1 += __shfl_xor_sync(0xffffffffu, lp1, 2);
    const float inv0 = 1.0f / lp0, inv1 = 1.0f / lp1;

    #pragma unroll
    for (int nd = 0; nd < 4; nd++) {
        const int col = half * 32 + nd * 8 + (l & 3) * 2;
        *(float2*)&g_a[((size_t)h * S_LEN + row0) * HD + col] =
            make_float2(O[nd][0] * inv0, O[nd][1] * inv0);
        *(float2*)&g_a[((size_t)h * S_LEN + row0 + 8) * HD + col] =
            make_float2(O[nd][2] * inv1, O[nd][3] * inv1);
    }
}

// -------- differential combine -> bf16 hi/lo --------
__global__ __launch_bounds__(512) void combine2(const float* __restrict__ lambda_p)
{
    const int m = blockIdx.x, t = threadIdx.x;
    const int h = t >> 5, j = t & 31;
    const float lam = lambda_p[h];
    const float* ap = g_a + ((size_t)h * S_LEN + m) * HD;
    const float a1 = ap[j], a2 = ap[j + 32];
    const float y1 = a1 - lam * a2, y2 = a1 + lam * a2;
    const size_t o1 = (size_t)m * DIM + h * HD + j, o2 = o1 + 32;
    split_bf(y1, g_yhi, g_ylo, o1);
    split_bf(y2, g_yhi, g_ylo, o2);
}

extern "C" void kernel_launch(void* const* d_in, const int* in_sizes, int n_in,
                              void* d_out, int out_size)
{
    const float* x        = (const float*)d_in[0];
    const float* Wq       = (const float*)d_in[1];
    const float* Wk       = (const float*)d_in[2];
    const float* Wv       = (const float*)d_in[3];
    const float* Wg       = (const float*)d_in[4];
    const float* Wo       = (const float*)d_in[5];
    const float* q_gain   = (const float*)d_in[6];
    const float* lambda_p = (const float*)d_in[7];
    float* out = (float*)d_out;

    cudaFuncSetAttribute(gemm_hmma3, cudaFuncAttributeMaxDynamicSharedMemorySize, GSMEM);
    cudaFuncSetAttribute(attn_mma, cudaFuncAttributeMaxDynamicSharedMemorySize, ASMEM);

    float* qkvg_p;
    __nv_bfloat16 *xhi, *xlo, *whi, *wlo, *wohi, *wolo, *yhi, *ylo;
    cudaGetSymbolAddress((void**)&qkvg_p, g_qkvg);
    cudaGetSymbolAddress((void**)&xhi, g_xhi);   cudaGetSymbolAddress((void**)&xlo, g_xlo);
    cudaGetSymbolAddress((void**)&whi, g_whi);   cudaGetSymbolAddress((void**)&wlo, g_wlo);
    cudaGetSymbolAddress((void**)&wohi, g_wohi); cudaGetSymbolAddress((void**)&wolo, g_wolo);
    cudaGetSymbolAddress((void**)&yhi, g_yhi);   cudaGetSymbolAddress((void**)&ylo, g_ylo);

    conv_all<<<4864, 256>>>(x, Wq, Wk, Wv, Wg, Wo);
    rotab<<<256, 256>>>();
    gemm_hmma3<<<dim3(NTOT/128, S_LEN/128), 256, GSMEM>>>(xhi, xlo, whi, wlo, qkvg_p, NTOT);
    postproc<<<dim3(S_LEN, 3), 256>>>(q_gain);
    attn_mma<<<dim3(S_LEN/128, NH, 2), 256, ASMEM>>>();
    combine2<<<S_LEN, 512>>>(lambda_p);
    gemm_hmma3<<<dim3(DIM/128, S_LEN/128), 256, GSMEM>>>(yhi, ylo, wohi, wolo, out, DIM);
}

// round 7
// speedup vs baseline: 5.4128x; 1.0078x over previous
#include <cuda_runtime.h>
#include <cuda_bf16.h>
#include <math.h>
#include <stdint.h>

#define S_LEN 2048
#define DIM 1024
#define NH 16
#define KVH 4
#define HD 64
#define NTOT 1792

__device__ float g_qkvg[S_LEN * NTOT];
__device__ float g_a[NH * S_LEN * HD];
__device__ float2 g_rot[S_LEN * 32];
__device__ __nv_bfloat16 g_xhi[S_LEN * DIM],  g_xlo[S_LEN * DIM];
__device__ __nv_bfloat16 g_whi[NTOT * DIM],   g_wlo[NTOT * DIM];
__device__ __nv_bfloat16 g_wohi[DIM * DIM],   g_wolo[DIM * DIM];
__device__ __nv_bfloat16 g_yhi[S_LEN * DIM],  g_ylo[S_LEN * DIM];
__device__ __nv_bfloat16 g_aqh[NH*2*S_LEN*32], g_aql[NH*2*S_LEN*32];
__device__ __nv_bfloat16 g_akh[KVH*2*S_LEN*32], g_akl[KVH*2*S_LEN*32];
__device__ __nv_bfloat16 g_avh[KVH*2*S_LEN*32], g_avl[KVH*2*S_LEN*32];

__device__ __forceinline__ uint32_t smem_u32(const void* p) {
    uint32_t a;
    asm("{ .reg .u64 t; cvta.to.shared.u64 t, %1; cvt.u32.u64 %0, t; }" : "=r"(a) : "l"(p));
    return a;
}
#define CP16(sm, gp) asm volatile("cp.async.cg.shared.global [%0], [%1], 16;" :: "r"(sm), "l"(gp))
#define LDSM4(r, addr) \
    asm volatile("ldmatrix.sync.aligned.m8n8.x4.shared.b16 {%0,%1,%2,%3}, [%4];" \
        : "=r"((r)[0]), "=r"((r)[1]), "=r"((r)[2]), "=r"((r)[3]) : "r"(addr))
#define LDSM4T(r, addr) \
    asm volatile("ldmatrix.sync.aligned.m8n8.x4.trans.shared.b16 {%0,%1,%2,%3}, [%4];" \
        : "=r"((r)[0]), "=r"((r)[1]), "=r"((r)[2]), "=r"((r)[3]) : "r"(addr))
#define MMA16816(d, a, b0, b1) \
    asm volatile("mma.sync.aligned.m16n8k16.row.col.f32.bf16.bf16.f32 " \
        "{%0,%1,%2,%3}, {%4,%5,%6,%7}, {%8,%9}, {%0,%1,%2,%3};" \
        : "+f"((d)[0]), "+f"((d)[1]), "+f"((d)[2]), "+f"((d)[3]) \
        : "r"((a)[0]), "r"((a)[1]), "r"((a)[2]), "r"((a)[3]), "r"(b0), "r"(b1))
#define PACKBF(r, a, b) asm("cvt.rn.bf16x2.f32 %0, %1, %2;" : "=r"(r) : "f"(b), "f"(a))
#define EX2(d, x) asm("ex2.approx.ftz.f32 %0, %1;" : "=f"(d) : "f"(x))

__device__ __forceinline__ void split_bf(float v, __nv_bfloat16* hi, __nv_bfloat16* lo,
                                         size_t o) {
    __nv_bfloat16 h = __float2bfloat16(v);
    hi[o] = h; lo[o] = __float2bfloat16(v - __bfloat162float(h));
}

// -------- fused fp32 -> bf16 hi/lo split for all 6 tensors --------
__global__ __launch_bounds__(256) void conv_all(
    const float* __restrict__ x,  const float* __restrict__ Wq,
    const float* __restrict__ Wk, const float* __restrict__ Wv,
    const float* __restrict__ Wg, const float* __restrict__ Wo)
{
    const int i = blockIdx.x * 256 + threadIdx.x;
    const float* s; __nv_bfloat16 *hi, *lo;
    if (i < 524288)      { size_t j = (size_t)i * 4;            s = x  + j; hi = g_xhi + j;            lo = g_xlo + j; }
    else if (i < 786432) { size_t j = (size_t)(i - 524288) * 4; s = Wq + j; hi = g_whi + j;            lo = g_wlo + j; }
    else if (i < 851968) { size_t j = (size_t)(i - 786432) * 4; s = Wk + j; hi = g_whi + 1048576 + j;  lo = g_wlo + 1048576 + j; }
    else if (i < 917504) { size_t j = (size_t)(i - 851968) * 4; s = Wv + j; hi = g_whi + 1310720 + j;  lo = g_wlo + 1310720 + j; }
    else if (i < 983040) { size_t j = (size_t)(i - 917504) * 4; s = Wg + j; hi = g_whi + 1572864 + j;  lo = g_wlo + 1572864 + j; }
    else                 { size_t j = (size_t)(i - 983040) * 4; s = Wo + j; hi = g_wohi + j;           lo = g_wolo + j; }
    float4 v = *(const float4*)s;
    __nv_bfloat16 a0 = __float2bfloat16(v.x), a1 = __float2bfloat16(v.y);
    __nv_bfloat16 a2 = __float2bfloat16(v.z), a3 = __float2bfloat16(v.w);
    __nv_bfloat162 h0, h1, l0, l1;
    h0.x = a0; h0.y = a1; h1.x = a2; h1.y = a3;
    l0.x = __float2bfloat16(v.x - __bfloat162float(a0));
    l0.y = __float2bfloat16(v.y - __bfloat162float(a1));
    l1.x = __float2bfloat16(v.z - __bfloat162float(a2));
    l1.y = __float2bfloat16(v.w - __bfloat162float(a3));
    *(__nv_bfloat162*)hi = h0; *(__nv_bfloat162*)(hi + 2) = h1;
    *(__nv_bfloat162*)lo = l0; *(__nv_bfloat162*)(lo + 2) = l1;
}

// -------- rotary table --------
__global__ __launch_bounds__(256) void rotab()
{
    const int i = blockIdx.x * 256 + threadIdx.x;
    const int m = i >> 5, t = i & 31;
    const float angle = ((float)(2 * t) / 64.0f) * 3.14159274101257324f;
    const float ang = (float)m * angle;
    double a = (double)ang;
    a -= rint(a * 0.15915494309189535) * 6.283185307179586;
    float c, sn;
    sincosf((float)a, &sn, &c);
    const float radius = 1.0f / (1.0f + (float)m * 0.01f);
    g_rot[i] = make_float2(c * radius, sn * radius);
}

// -------- HMMA bf16x3 GEMM --------
#define AST   18432
#define STG_B (4 * AST)
#define GSMEM (2 * STG_B)

__device__ __forceinline__ void g_load_stage(
    uint32_t sb, const char* pAhi, const char* pAlo,
    const char* pBhi, const char* pBlo, int t, int s)
{
    const size_t gk = (size_t)s * 128;
    #pragma unroll
    for (int j = 0; j < 4; j++) {
        const int c = t + 256 * j;
        const int row = c >> 3, kc = c & 7;
        const size_t go = (size_t)row * 2048 + gk + kc * 16;
        const uint32_t so = row * 144 + kc * 16;
        CP16(sb +          so, pAhi + go);
        CP16(sb +   AST  + so, pAlo + go);
        CP16(sb + 2*AST  + so, pBhi + go);
        CP16(sb + 3*AST  + so, pBlo + go);
    }
    asm volatile("cp.async.commit_group;" ::: "memory");
}

__global__ __launch_bounds__(256) void gemm_hmma3(
    const __nv_bfloat16* __restrict__ Ahi, const __nv_bfloat16* __restrict__ Alo,
    const __nv_bfloat16* __restrict__ Bhi, const __nv_bfloat16* __restrict__ Blo,
    float* __restrict__ C, int ldc)
{
    extern __shared__ char sm[];
    const int t = threadIdx.x, wid = t >> 5, lane = t & 31;
    const int m0 = blockIdx.y * 128, nb = blockIdx.x * 128;
    const uint32_t smb = smem_u32(sm);

    const char* pAhi = (const char*)Ahi + (size_t)m0 * 2048;
    const char* pAlo = (const char*)Alo + (size_t)m0 * 2048;
    const char* pBhi = (const char*)Bhi + (size_t)nb * 2048;
    const char* pBlo = (const char*)Blo + (size_t)nb * 2048;

    const int warp_m = (wid & 1) * 64;
    const int warp_n = (wid >> 1) * 32;
    const int a_m  = lane & 15;
    const int a_kb = lane >> 4;
    const int b_n  = (lane & 7) + ((lane >> 4) & 1) * 8;
    const int b_kb = (lane >> 3) & 1;

    float acc[4][4][4];
    #pragma unroll
    for (int im = 0; im < 4; im++)
        #pragma unroll
        for (int jn = 0; jn < 4; jn++)
            #pragma unroll
            for (int c = 0; c < 4; c++) acc[im][jn][c] = 0.0f;

    g_load_stage(smb,         pAhi, pAlo, pBhi, pBlo, t, 0);
    g_load_stage(smb + STG_B, pAhi, pAlo, pBhi, pBlo, t, 1);

    #pragma unroll 1
    for (int s = 0; s < 16; s++) {
        const int b = s & 1;
        if (s < 15) asm volatile("cp.async.wait_group 1;" ::: "memory");
        else        asm volatile("cp.async.wait_group 0;" ::: "memory");
        __syncthreads();

        const uint32_t sb = smb + b * STG_B;
        #pragma unroll
        for (int kk = 0; kk < 4; kk++) {
            const uint32_t k0 = kk * 16;
            uint32_t ahi[4][4], alo[4][4], bhi[2][4], blo[2][4];
            const uint32_t aoff = (warp_m + a_m) * 144 + (k0 + a_kb * 8) * 2;
            #pragma unroll
            for (int im = 0; im < 4; im++) {
                LDSM4(ahi[im], sb +       aoff + im * (16 * 144));
                LDSM4(alo[im], sb + AST + aoff + im * (16 * 144));
            }
            #pragma unroll
            for (int j2 = 0; j2 < 2; j2++) {
                const uint32_t boff = (warp_n + j2 * 16 + b_n) * 144 + (k0 + b_kb * 8) * 2;
                LDSM4(bhi[j2], sb + 2*AST + boff);
                LDSM4(blo[j2], sb + 3*AST + boff);
            }
            #pragma unroll
            for (int im = 0; im < 4; im++)
                #pragma unroll
                for (int jn = 0; jn < 4; jn++) {
                    const int j2 = jn >> 1, jr = (jn & 1) * 2;
                    MMA16816(acc[im][jn], ahi[im], bhi[j2][jr], bhi[j2][jr + 1]);
                    MMA16816(acc[im][jn], ahi[im], blo[j2][jr], blo[j2][jr + 1]);
                    MMA16816(acc[im][jn], alo[im], bhi[j2][jr], bhi[j2][jr + 1]);
                }
        }
        __syncthreads();
        if (s + 2 < 16) g_load_stage(sb, pAhi, pAlo, pBhi, pBlo, t, s + 2);
    }

    const int r0 = lane >> 2, c0 = (lane & 3) * 2;
    #pragma unroll
    for (int im = 0; im < 4; im++)
        #pragma unroll
        for (int jn = 0; jn < 4; jn++) {
            const int row = m0 + warp_m + im * 16 + r0;
            const int col = nb + warp_n + jn * 8 + c0;
            *(float2*)&C[(size_t)row * ldc + col] =
                make_float2(acc[im][jn][0], acc[im][jn][1]);
            *(float2*)&C[(size_t)(row + 8) * ldc + col] =
                make_float2(acc[im][jn][2], acc[im][jn][3]);
        }
}

// -------- postprocess: warp-per-unit, 4 tokens per block --------
#define LOG2E 1.4426950408889634f
__global__ __launch_bounds__(256) void postproc(const float* __restrict__ q_gain)
{
    const int w = threadIdx.x >> 5, l = threadIdx.x & 31;
    const int unit = blockIdx.y * 8 + w;
    if (unit >= 21) return;

    #pragma unroll
    for (int mi = 0; mi < 4; mi++) {
        const int m = blockIdx.x * 4 + mi;
        const float* row = g_qkvg + (size_t)m * NTOT;

        if (unit == 20) {
            #pragma unroll
            for (int i = l; i < 256; i += 32) {
                float v = row[1280 + i], g = row[1536 + i];
                float vg = v / (1.0f + __expf(-g));
                int kvh = i >> 6, d = i & 63, hf = d >> 5, dc = d & 31;
                size_t o = ((size_t)(kvh * 2 + hf) * S_LEN + m) * 32 + dc;
                split_bf(vg, g_avh, g_avl, o);
            }
            continue;
        }
        const bool isq = unit < 16;
        const int h = isq ? unit : unit - 16;
        const int col0 = isq ? h * HD : 1024 + h * HD;
        float x1 = row[col0 + l], x2 = row[col0 + l + 32];
        float ss = x1 * x1 + x2 * x2;
        #pragma unroll
        for (int o = 16; o > 0; o >>= 1) ss += __shfl_xor_sync(0xffffffffu, ss, o);
        const float rn = rsqrtf(ss * (1.0f / 64.0f) + 1.1920929e-7f);
        x1 *= rn; x2 *= rn;
        const float2 rc = g_rot[m * 32 + l];
        float y0 = x1 * rc.x + x2 * rc.y;
        float y1 = -x1 * rc.y + x2 * rc.x;
        const size_t o0 = ((size_t)(h * 2 + 0) * S_LEN + m) * 32 + l;
        const size_t o1 = ((size_t)(h * 2 + 1) * S_LEN + m) * 32 + l;
        if (isq) {
            const float gs = q_gain[h] * (0.17677669529663688f * LOG2E);
            y0 *= gs; y1 *= gs;
            split_bf(y0, g_aqh, g_aql, o0);
            split_bf(y1, g_aqh, g_aql, o1);
        } else {
            split_bf(y0, g_akh, g_akl, o0);
            split_bf(y1, g_akh, g_akl, o1);
        }
    }
}

// -------- HMMA flash attention: fixed-base exp2 softmax (no online max) ----
// Valid because q,k are RMS-normed: |score*log2e| <= ~8.2, exp2 never overflows.
#define ATILE 5120
#define QTILE 10240
#define AKV   (4 * ATILE)
#define ASMEM (2 * AKV + 2 * QTILE)    // 61440

__device__ __forceinline__ void a_load_kv(
    uint32_t sb, const char* kh, const char* kl,
    const char* vh, const char* vl, int t, int key0)
{
    const char* base[4] = { kh, kl, vh, vl };
    #pragma unroll
    for (int j = 0; j < 4; j++) {
        const int c = t + 256 * j;
        const int arr = c >> 8, rem = c & 255;
        const int row = rem >> 2, c4 = rem & 3;
        CP16(sb + arr * ATILE + row * 80 + c4 * 16,
             base[arr] + ((size_t)(key0 + row) * 32 + c4 * 8) * 2);
    }
    asm volatile("cp.async.commit_group;" ::: "memory");
}

__global__ __launch_bounds__(256) void attn_mma()
{
    extern __shared__ char sm[];
    const int qt = gridDim.x - 1 - blockIdx.x;
    const int h = blockIdx.y, half = blockIdx.z, kvh = h >> 2;
    const int t = threadIdx.x, w = t >> 5, l = t & 31;
    const int q0 = qt * 128;
    const uint32_t smb = smem_u32(sm);
    const uint32_t sQh = smb + 2 * AKV, sQl = sQh + QTILE;

    const char* qh_g = (const char*)(g_aqh + ((size_t)(h * 2 + half) * S_LEN + q0) * 32);
    const char* ql_g = (const char*)(g_aql + ((size_t)(h * 2 + half) * S_LEN + q0) * 32);
    const char* kh_g = (const char*)(g_akh + (size_t)(kvh * 2 + half) * S_LEN * 32);
    const char* kl_g = (const char*)(g_akl + (size_t)(kvh * 2 + half) * S_LEN * 32);
    const char* vh_g = (const char*)(g_avh + (size_t)(kvh * 2 + half) * S_LEN * 32);
    const char* vl_g = (const char*)(g_avl + (size_t)(kvh * 2 + half) * S_LEN * 32);

    #pragma unroll
    for (int j = 0; j < 4; j++) {
        const int c = t + 256 * j;
        const int arr = c >> 9, rem = c & 511;
        const int row = rem >> 2, c4 = rem & 3;
        CP16((arr ? sQl : sQh) + row * 80 + c4 * 16,
             (arr ? ql_g : qh_g) + ((size_t)row * 32 + c4 * 8) * 2);
    }
    a_load_kv(smb, kh_g, kl_g, vh_g, vl_g, t, 0);
    const int nt = 2 * qt + 2;
    if (nt > 1) a_load_kv(smb + AKV, kh_g, kl_g, vh_g, vl_g, t, 64);

    uint32_t qh[2][4], ql[2][4];
    float O[4][4];
    #pragma unroll
    for (int nd = 0; nd < 4; nd++)
        #pragma unroll
        for (int c = 0; c < 4; c++) O[nd][c] = 0.0f;
    float lp0 = 0.0f, lp1 = 0.0f;

    const int row0 = q0 + w * 16 + (l >> 2);
    const int qmax_w = q0 + w * 16 + 15;
    const int qmin_w = q0 + w * 16;

    #pragma unroll 1
    for (int i = 0; i < nt; i++) {
        if (i + 1 < nt) asm volatile("cp.async.wait_group 1;" ::: "memory");
        else            asm volatile("cp.async.wait_group 0;" ::: "memory");
        __syncthreads();

        if (i == 0) {
            const uint32_t qoff = (w * 16 + (l & 15)) * 80 + ((l >> 4) * 8) * 2;
            LDSM4(qh[0], sQh + qoff);       LDSM4(qh[1], sQh + qoff + 32);
            LDSM4(ql[0], sQl + qoff);       LDSM4(ql[1], sQl + qoff + 32);
        }

        const uint32_t sb = smb + (i & 1) * AKV;
        const int key0 = i * 64;

        if (key0 <= qmax_w) {
            float s[8][4];
            #pragma unroll
            for (int n = 0; n < 8; n++)
                #pragma unroll
                for (int c = 0; c < 4; c++) s[n][c] = 0.0f;

            #pragma unroll
            for (int ks = 0; ks < 2; ks++) {
                #pragma unroll
                for (int g = 0; g < 4; g++) {
                    uint32_t kh[4], kl[4];
                    const uint32_t ka = sb
                        + (g * 16 + (l & 7) + ((l >> 4) & 1) * 8) * 80
                        + (ks * 16 + ((l >> 3) & 1) * 8) * 2;
                    LDSM4(kh, ka);
                    LDSM4(kl, ka + ATILE);
                    MMA16816(s[2*g],   qh[ks], kh[0], kh[1]);
                    MMA16816(s[2*g],   qh[ks], kl[0], kl[1]);
                    MMA16816(s[2*g],   ql[ks], kh[0], kh[1]);
                    MMA16816(s[2*g+1], qh[ks], kh[2], kh[3]);
                    MMA16816(s[2*g+1], qh[ks], kl[2], kl[3]);
                    MMA16816(s[2*g+1], ql[ks], kh[2], kh[3]);
                }
            }

            if (key0 + 63 > qmin_w) {
                #pragma unroll
                for (int n = 0; n < 8; n++) {
                    const int cb = key0 + n * 8 + (l & 3) * 2;
                    if (cb     > row0)     s[n][0] = -1e30f;
                    if (cb + 1 > row0)     s[n][1] = -1e30f;
                    if (cb     > row0 + 8) s[n][2] = -1e30f;
                    if (cb + 1 > row0 + 8) s[n][3] = -1e30f;
                }
            }

            // fixed-base softmax: p = exp2(s) directly; bounded since inputs RMS-normed
            uint32_t aPh[4][4], aPl[4][4];
            #pragma unroll
            for (int j = 0; j < 4; j++) {
                #pragma unroll
                for (int q = 0; q < 2; q++) {
                    const int n = 2 * j + q;
                    float p0, p1, p2, p3;
                    EX2(p0, s[n][0]);
                    EX2(p1, s[n][1]);
                    EX2(p2, s[n][2]);
                    EX2(p3, s[n][3]);
                    lp0 += p0 + p1; lp1 += p2 + p3;
                    uint32_t h01, h23;
                    PACKBF(h01, p0, p1);
                    PACKBF(h23, p2, p3);
                    aPh[j][2*q]   = h01;
                    aPh[j][2*q+1] = h23;
                    float f0 = __uint_as_float(h01 << 16);
                    float f1 = __uint_as_float(h01 & 0xffff0000u);
                    float f2 = __uint_as_float(h23 << 16);
                    float f3 = __uint_as_float(h23 & 0xffff0000u);
                    uint32_t l01, l23;
                    PACKBF(l01, p0 - f0, p1 - f1);
                    PACKBF(l23, p2 - f2, p3 - f3);
                    aPl[j][2*q]   = l01;
                    aPl[j][2*q+1] = l23;
                }
            }

            #pragma unroll
            for (int j = 0; j < 4; j++) {
                #pragma unroll
                for (int dg = 0; dg < 2; dg++) {
                    uint32_t vh[4], vl[4];
                    const uint32_t va = sb + 2 * ATILE
                        + (16 * j + (l & 7) + ((l >> 3) & 1) * 8) * 80
                        + (dg * 16 + ((l >> 4) & 1) * 8) * 2;
                    LDSM4T(vh, va);
                    LDSM4T(vl, va + ATILE);
                    MMA16816(O[2*dg],   aPh[j], vh[0], vh[1]);
                    MMA16816(O[2*dg],   aPh[j], vl[0], vl[1]);
                    MMA16816(O[2*dg],   aPl[j], vh[0], vh[1]);
                    MMA16816(O[2*dg+1], aPh[j], vh[2], vh[3]);
                    MMA16816(O[2*dg+1], aPh[j], vl[2], vl[3]);
                    MMA16816(O[2*dg+1], aPl[j], vh[2], vh[3]);
                }
            }
        }

        __syncthreads();
        if (i + 2 < nt)
            a_load_kv(sb, kh_g, kl_g, vh_g, vl_g, t, (i + 2) * 64);
    }

    lp0 += __shfl_xor_sync(0xffffffffu, lp0, 1);
    lp0 += __shfl_xor_sync(0xffffffffu, lp0, 2);
    lp1 += __shfl_xor_sync(0xffffffffu, lp1, 1);
    lp1 += __shfl_xor_sync(0xffffffffu, lp1, 2);
    const float inv0 = 1.0f / lp0, inv1 = 1.0f / lp1;

    #pragma unroll
    for (int nd = 0; nd < 4; nd++) {
        const int col = half * 32 + nd * 8 + (l & 3) * 2;
        *(float2*)&g_a[((size_t)h * S_LEN + row0) * HD + col] =
            make_float2(O[nd][0] * inv0, O[nd][1] * inv0);
        *(float2*)&g_a[((size_t)h * S_LEN + row0 + 8) * HD + col] =
            make_float2(O[nd][2] * inv1, O[nd][3] * inv1);
    }
}

// -------- differential combine, 4 tokens per block --------
__global__ __launch_bounds__(512) void combine2(const float* __restrict__ lambda_p)
{
    const int t = threadIdx.x;
    const int h = t >> 5, j = t & 31;
    const float lam = lambda_p[h];
    #pragma unroll
    for (int mi = 0; mi < 4; mi++) {
        const int m = blockIdx.x * 4 + mi;
        const float* ap = g_a + ((size_t)h * S_LEN + m) * HD;
        const float a1 = ap[j], a2 = ap[j + 32];
        const float y1 = a1 - lam * a2, y2 = a1 + lam * a2;
        const size_t o1 = (size_t)m * DIM + h * HD + j, o2 = o1 + 32;
        split_bf(y1, g_yhi, g_ylo, o1);
        split_bf(y2, g_yhi, g_ylo, o2);
    }
}

extern "C" void kernel_launch(void* const* d_in, const int* in_sizes, int n_in,
                              void* d_out, int out_size)
{
    const float* x        = (const float*)d_in[0];
    const float* Wq       = (const float*)d_in[1];
    const float* Wk       = (const float*)d_in[2];
    const float* Wv       = (const float*)d_in[3];
    const float* Wg       = (const float*)d_in[4];
    const float* Wo       = (const float*)d_in[5];
    const float* q_gain   = (const float*)d_in[6];
    const float* lambda_p = (const float*)d_in[7];
    float* out = (float*)d_out;

    cudaFuncSetAttribute(gemm_hmma3, cudaFuncAttributeMaxDynamicSharedMemorySize, GSMEM);
    cudaFuncSetAttribute(attn_mma, cudaFuncAttributeMaxDynamicSharedMemorySize, ASMEM);

    float* qkvg_p;
    __nv_bfloat16 *xhi, *xlo, *whi, *wlo, *wohi, *wolo, *yhi, *ylo;
    cudaGetSymbolAddress((void**)&qkvg_p, g_qkvg);
    cudaGetSymbolAddress((void**)&xhi, g_xhi);   cudaGetSymbolAddress((void**)&xlo, g_xlo);
    cudaGetSymbolAddress((void**)&whi, g_whi);   cudaGetSymbolAddress((void**)&wlo, g_wlo);
    cudaGetSymbolAddress((void**)&wohi, g_wohi); cudaGetSymbolAddress((void**)&wolo, g_wolo);
    cudaGetSymbolAddress((void**)&yhi, g_yhi);   cudaGetSymbolAddress((void**)&ylo, g_ylo);

    conv_all<<<4864, 256>>>(x, Wq, Wk, Wv, Wg, Wo);
    rotab<<<256, 256>>>();
    gemm_hmma3<<<dim3(NTOT/128, S_LEN/128), 256, GSMEM>>>(xhi, xlo, whi, wlo, qkvg_p, NTOT);
    postproc<<<dim3(S_LEN/4, 3), 256>>>(q_gain);
    attn_mma<<<dim3(S_LEN/128, NH, 2), 256, ASMEM>>>();
    combine2<<<S_LEN/4, 512>>>(lambda_p);
    gemm_hmma3<<<dim3(DIM/128, S_LEN/128), 256, GSMEM>>>(yhi, ylo, wohi, wolo, out, DIM);
}

// round 8
// speedup vs baseline: 5.5733x; 1.0297x over previous
#include <cuda_runtime.h>
#include <cuda_bf16.h>
#include <math.h>
#include <stdint.h>

#define S_LEN 2048
#define DIM 1024
#define NH 16
#define KVH 4
#define HD 64
#define NTOT 1792

__device__ float g_qkvg[S_LEN * NTOT];
__device__ float g_a[NH * S_LEN * HD];
__device__ float2 g_rot[S_LEN * 32];
__device__ __nv_bfloat16 g_xhi[S_LEN * DIM],  g_xlo[S_LEN * DIM];
__device__ __nv_bfloat16 g_whi[NTOT * DIM],   g_wlo[NTOT * DIM];
__device__ __nv_bfloat16 g_wohi[DIM * DIM],   g_wolo[DIM * DIM];
__device__ __nv_bfloat16 g_yhi[S_LEN * DIM],  g_ylo[S_LEN * DIM];
__device__ __nv_bfloat16 g_aqh[NH*2*S_LEN*32], g_aql[NH*2*S_LEN*32];
__device__ __nv_bfloat16 g_akh[KVH*2*S_LEN*32], g_akl[KVH*2*S_LEN*32];
__device__ __nv_bfloat16 g_avh[KVH*2*S_LEN*32], g_avl[KVH*2*S_LEN*32];

__device__ __forceinline__ uint32_t smem_u32(const void* p) {
    uint32_t a;
    asm("{ .reg .u64 t; cvta.to.shared.u64 t, %1; cvt.u32.u64 %0, t; }" : "=r"(a) : "l"(p));
    return a;
}
#define CP16(sm, gp) asm volatile("cp.async.cg.shared.global [%0], [%1], 16;" :: "r"(sm), "l"(gp))
#define LDSM4(r, addr) \
    asm volatile("ldmatrix.sync.aligned.m8n8.x4.shared.b16 {%0,%1,%2,%3}, [%4];" \
        : "=r"((r)[0]), "=r"((r)[1]), "=r"((r)[2]), "=r"((r)[3]) : "r"(addr))
#define LDSM4T(r, addr) \
    asm volatile("ldmatrix.sync.aligned.m8n8.x4.trans.shared.b16 {%0,%1,%2,%3}, [%4];" \
        : "=r"((r)[0]), "=r"((r)[1]), "=r"((r)[2]), "=r"((r)[3]) : "r"(addr))
#define MMA16816(d, a, b0, b1) \
    asm volatile("mma.sync.aligned.m16n8k16.row.col.f32.bf16.bf16.f32 " \
        "{%0,%1,%2,%3}, {%4,%5,%6,%7}, {%8,%9}, {%0,%1,%2,%3};" \
        : "+f"((d)[0]), "+f"((d)[1]), "+f"((d)[2]), "+f"((d)[3]) \
        : "r"((a)[0]), "r"((a)[1]), "r"((a)[2]), "r"((a)[3]), "r"(b0), "r"(b1))
#define PACKBF(r, a, b) asm("cvt.rn.bf16x2.f32 %0, %1, %2;" : "=r"(r) : "f"(b), "f"(a))
#define EX2(d, x) asm("ex2.approx.ftz.f32 %0, %1;" : "=f"(d) : "f"(x))

__device__ __forceinline__ void split_bf(float v, __nv_bfloat16* hi, __nv_bfloat16* lo,
                                         size_t o) {
    __nv_bfloat16 h = __float2bfloat16(v);
    hi[o] = h; lo[o] = __float2bfloat16(v - __bfloat162float(h));
}

// -------- fused fp32 -> bf16 hi/lo split for all 6 tensors --------
__global__ __launch_bounds__(256) void conv_all(
    const float* __restrict__ x,  const float* __restrict__ Wq,
    const float* __restrict__ Wk, const float* __restrict__ Wv,
    const float* __restrict__ Wg, const float* __restrict__ Wo)
{
    const int i = blockIdx.x * 256 + threadIdx.x;
    const float* s; __nv_bfloat16 *hi, *lo;
    if (i < 524288)      { size_t j = (size_t)i * 4;            s = x  + j; hi = g_xhi + j;            lo = g_xlo + j; }
    else if (i < 786432) { size_t j = (size_t)(i - 524288) * 4; s = Wq + j; hi = g_whi + j;            lo = g_wlo + j; }
    else if (i < 851968) { size_t j = (size_t)(i - 786432) * 4; s = Wk + j; hi = g_whi + 1048576 + j;  lo = g_wlo + 1048576 + j; }
    else if (i < 917504) { size_t j = (size_t)(i - 851968) * 4; s = Wv + j; hi = g_whi + 1310720 + j;  lo = g_wlo + 1310720 + j; }
    else if (i < 983040) { size_t j = (size_t)(i - 917504) * 4; s = Wg + j; hi = g_whi + 1572864 + j;  lo = g_wlo + 1572864 + j; }
    else                 { size_t j = (size_t)(i - 983040) * 4; s = Wo + j; hi = g_wohi + j;           lo = g_wolo + j; }
    float4 v = *(const float4*)s;
    __nv_bfloat16 a0 = __float2bfloat16(v.x), a1 = __float2bfloat16(v.y);
    __nv_bfloat16 a2 = __float2bfloat16(v.z), a3 = __float2bfloat16(v.w);
    __nv_bfloat162 h0, h1, l0, l1;
    h0.x = a0; h0.y = a1; h1.x = a2; h1.y = a3;
    l0.x = __float2bfloat16(v.x - __bfloat162float(a0));
    l0.y = __float2bfloat16(v.y - __bfloat162float(a1));
    l1.x = __float2bfloat16(v.z - __bfloat162float(a2));
    l1.y = __float2bfloat16(v.w - __bfloat162float(a3));
    *(__nv_bfloat162*)hi = h0; *(__nv_bfloat162*)(hi + 2) = h1;
    *(__nv_bfloat162*)lo = l0; *(__nv_bfloat162*)(lo + 2) = l1;
}

// -------- rotary table --------
__global__ __launch_bounds__(256) void rotab()
{
    const int i = blockIdx.x * 256 + threadIdx.x;
    const int m = i >> 5, t = i & 31;
    const float angle = ((float)(2 * t) / 64.0f) * 3.14159274101257324f;
    const float ang = (float)m * angle;
    double a = (double)ang;
    a -= rint(a * 0.15915494309189535) * 6.283185307179586;
    float c, sn;
    sincosf((float)a, &sn, &c);
    const float radius = 1.0f / (1.0f + (float)m * 0.01f);
    g_rot[i] = make_float2(c * radius, sn * radius);
}

// -------- HMMA bf16x3 GEMM, 3-stage pipeline --------
#define AST   18432
#define STG_B (4 * AST)
#define GSMEM (3 * STG_B)          // 221184

__device__ __forceinline__ void g_load_stage(
    uint32_t sb, const char* pAhi, const char* pAlo,
    const char* pBhi, const char* pBlo, int t, int s)
{
    const size_t gk = (size_t)s * 128;
    #pragma unroll
    for (int j = 0; j < 4; j++) {
        const int c = t + 256 * j;
        const int row = c >> 3, kc = c & 7;
        const size_t go = (size_t)row * 2048 + gk + kc * 16;
        const uint32_t so = row * 144 + kc * 16;
        CP16(sb +          so, pAhi + go);
        CP16(sb +   AST  + so, pAlo + go);
        CP16(sb + 2*AST  + so, pBhi + go);
        CP16(sb + 3*AST  + so, pBlo + go);
    }
    asm volatile("cp.async.commit_group;" ::: "memory");
}

__global__ __launch_bounds__(256) void gemm_hmma3(
    const __nv_bfloat16* __restrict__ Ahi, const __nv_bfloat16* __restrict__ Alo,
    const __nv_bfloat16* __restrict__ Bhi, const __nv_bfloat16* __restrict__ Blo,
    float* __restrict__ C, int ldc)
{
    extern __shared__ char sm[];
    const int t = threadIdx.x, wid = t >> 5, lane = t & 31;
    const int m0 = blockIdx.y * 128, nb = blockIdx.x * 128;
    const uint32_t smb = smem_u32(sm);

    const char* pAhi = (const char*)Ahi + (size_t)m0 * 2048;
    const char* pAlo = (const char*)Alo + (size_t)m0 * 2048;
    const char* pBhi = (const char*)Bhi + (size_t)nb * 2048;
    const char* pBlo = (const char*)Blo + (size_t)nb * 2048;

    const int warp_m = (wid & 1) * 64;
    const int warp_n = (wid >> 1) * 32;
    const int a_m  = lane & 15;
    const int a_kb = lane >> 4;
    const int b_n  = (lane & 7) + ((lane >> 4) & 1) * 8;
    const int b_kb = (lane >> 3) & 1;

    float acc[4][4][4];
    #pragma unroll
    for (int im = 0; im < 4; im++)
        #pragma unroll
        for (int jn = 0; jn < 4; jn++)
            #pragma unroll
            for (int c = 0; c < 4; c++) acc[im][jn][c] = 0.0f;

    g_load_stage(smb,             pAhi, pAlo, pBhi, pBlo, t, 0);
    g_load_stage(smb + STG_B,     pAhi, pAlo, pBhi, pBlo, t, 1);
    g_load_stage(smb + 2 * STG_B, pAhi, pAlo, pBhi, pBlo, t, 2);

    int buf = 0;
    #pragma unroll 1
    for (int s = 0; s < 16; s++) {
        if (s < 14)       asm volatile("cp.async.wait_group 2;" ::: "memory");
        else if (s == 14) asm volatile("cp.async.wait_group 1;" ::: "memory");
        else              asm volatile("cp.async.wait_group 0;" ::: "memory");
        __syncthreads();

        const uint32_t sb = smb + buf * STG_B;
        #pragma unroll
        for (int kk = 0; kk < 4; kk++) {
            const uint32_t k0 = kk * 16;
            uint32_t ahi[4][4], alo[4][4], bhi[2][4], blo[2][4];
            const uint32_t aoff = (warp_m + a_m) * 144 + (k0 + a_kb * 8) * 2;
            #pragma unroll
            for (int im = 0; im < 4; im++) {
                LDSM4(ahi[im], sb +       aoff + im * (16 * 144));
                LDSM4(alo[im], sb + AST + aoff + im * (16 * 144));
            }
            #pragma unroll
            for (int j2 = 0; j2 < 2; j2++) {
                const uint32_t boff = (warp_n + j2 * 16 + b_n) * 144 + (k0 + b_kb * 8) * 2;
                LDSM4(bhi[j2], sb + 2*AST + boff);
                LDSM4(blo[j2], sb + 3*AST + boff);
            }
            #pragma unroll
            for (int im = 0; im < 4; im++)
                #pragma unroll
                for (int jn = 0; jn < 4; jn++) {
                    const int j2 = jn >> 1, jr = (jn & 1) * 2;
                    MMA16816(acc[im][jn], ahi[im], bhi[j2][jr], bhi[j2][jr + 1]);
                    MMA16816(acc[im][jn], ahi[im], blo[j2][jr], blo[j2][jr + 1]);
                    MMA16816(acc[im][jn], alo[im], bhi[j2][jr], bhi[j2][jr + 1]);
                }
        }
        __syncthreads();
        if (s + 3 < 16) g_load_stage(sb, pAhi, pAlo, pBhi, pBlo, t, s + 3);
        buf = (buf == 2) ? 0 : buf + 1;
    }

    const int r0 = lane >> 2, c0 = (lane & 3) * 2;
    #pragma unroll
    for (int im = 0; im < 4; im++)
        #pragma unroll
        for (int jn = 0; jn < 4; jn++) {
            const int row = m0 + warp_m + im * 16 + r0;
            const int col = nb + warp_n + jn * 8 + c0;
            *(float2*)&C[(size_t)row * ldc + col] =
                make_float2(acc[im][jn][0], acc[im][jn][1]);
            *(float2*)&C[(size_t)(row + 8) * ldc + col] =
                make_float2(acc[im][jn][2], acc[im][jn][3]);
        }
}

// -------- postprocess q/k: grid (S, 5) x 128 threads, warp = one unit --------
#define LOG2E 1.4426950408889634f
__global__ __launch_bounds__(128) void pp_qk(const float* __restrict__ q_gain)
{
    const int m = blockIdx.x;
    const int w = threadIdx.x >> 5, l = threadIdx.x & 31;
    const int unit = blockIdx.y * 4 + w;          // 0..19
    const float* row = g_qkvg + (size_t)m * NTOT;

    const bool isq = unit < 16;
    const int h = isq ? unit : unit - 16;
    const int col0 = isq ? h * HD : 1024 + h * HD;
    float x1 = row[col0 + l], x2 = row[col0 + l + 32];
    float ss = x1 * x1 + x2 * x2;
    #pragma unroll
    for (int o = 16; o > 0; o >>= 1) ss += __shfl_xor_sync(0xffffffffu, ss, o);
    const float rn = rsqrtf(ss * (1.0f / 64.0f) + 1.1920929e-7f);
    x1 *= rn; x2 *= rn;
    const float2 rc = g_rot[m * 32 + l];
    float y0 = x1 * rc.x + x2 * rc.y;
    float y1 = -x1 * rc.y + x2 * rc.x;
    const size_t o0 = ((size_t)(h * 2 + 0) * S_LEN + m) * 32 + l;
    const size_t o1 = ((size_t)(h * 2 + 1) * S_LEN + m) * 32 + l;
    if (isq) {
        const float gs = q_gain[h] * (0.17677669529663688f * LOG2E);
        y0 *= gs; y1 *= gs;
        split_bf(y0, g_aqh, g_aql, o0);
        split_bf(y1, g_aqh, g_aql, o1);
    } else {
        split_bf(y0, g_akh, g_akl, o0);
        split_bf(y1, g_akh, g_akl, o1);
    }
}

// -------- v-gate: elementwise, 1 thread = 1 element --------
__global__ __launch_bounds__(256) void pp_vgate()
{
    const int m = blockIdx.x, i = threadIdx.x;    // i < 256
    const float* row = g_qkvg + (size_t)m * NTOT;
    float v = row[1280 + i], g = row[1536 + i];
    float vg = v / (1.0f + __expf(-g));
    int kvh = i >> 6, d = i & 63, hf = d >> 5, dc = d & 31;
    size_t o = ((size_t)(kvh * 2 + hf) * S_LEN + m) * 32 + dc;
    split_bf(vg, g_avh, g_avl, o);
}

// -------- HMMA flash attention (fixed-base exp2 softmax) --------
#define ATILE 5120
#define QTILE 10240
#define AKV   (4 * ATILE)
#define ASMEM (2 * AKV + 2 * QTILE)    // 61440

__device__ __forceinline__ void a_load_kv(
    uint32_t sb, const char* kh, const char* kl,
    const char* vh, const char* vl, int t, int key0)
{
    const char* base[4] = { kh, kl, vh, vl };
    #pragma unroll
    for (int j = 0; j < 4; j++) {
        const int c = t + 256 * j;
        const int arr = c >> 8, rem = c & 255;
        const int row = rem >> 2, c4 = rem & 3;
        CP16(sb + arr * ATILE + row * 80 + c4 * 16,
             base[arr] + ((size_t)(key0 + row) * 32 + c4 * 8) * 2);
    }
    asm volatile("cp.async.commit_group;" ::: "memory");
}

__global__ __launch_bounds__(256) void attn_mma()
{
    extern __shared__ char sm[];
    const int qt = gridDim.x - 1 - blockIdx.x;
    const int h = blockIdx.y, half = blockIdx.z, kvh = h >> 2;
    const int t = threadIdx.x, w = t >> 5, l = t & 31;
    const int q0 = qt * 128;
    const uint32_t smb = smem_u32(sm);
    const uint32_t sQh = smb + 2 * AKV, sQl = sQh + QTILE;

    const char* qh_g = (const char*)(g_aqh + ((size_t)(h * 2 + half) * S_LEN + q0) * 32);
    const char* ql_g = (const char*)(g_aql + ((size_t)(h * 2 + half) * S_LEN + q0) * 32);
    const char* kh_g = (const char*)(g_akh + (size_t)(kvh * 2 + half) * S_LEN * 32);
    const char* kl_g = (const char*)(g_akl + (size_t)(kvh * 2 + half) * S_LEN * 32);
    const char* vh_g = (const char*)(g_avh + (size_t)(kvh * 2 + half) * S_LEN * 32);
    const char* vl_g = (const char*)(g_avl + (size_t)(kvh * 2 + half) * S_LEN * 32);

    #pragma unroll
    for (int j = 0; j < 4; j++) {
        const int c = t + 256 * j;
        const int arr = c >> 9, rem = c & 511;
        const int row = rem >> 2, c4 = rem & 3;
        CP16((arr ? sQl : sQh) + row * 80 + c4 * 16,
             (arr ? ql_g : qh_g) + ((size_t)row * 32 + c4 * 8) * 2);
    }
    a_load_kv(smb, kh_g, kl_g, vh_g, vl_g, t, 0);
    const int nt = 2 * qt + 2;
    if (nt > 1) a_load_kv(smb + AKV, kh_g, kl_g, vh_g, vl_g, t, 64);

    uint32_t qh[2][4], ql[2][4];
    float O[4][4];
    #pragma unroll
    for (int nd = 0; nd < 4; nd++)
        #pragma unroll
        for (int c = 0; c < 4; c++) O[nd][c] = 0.0f;
    float lp0 = 0.0f, lp1 = 0.0f;

    const int row0 = q0 + w * 16 + (l >> 2);
    const int qmax_w = q0 + w * 16 + 15;
    const int qmin_w = q0 + w * 16;

    #pragma unroll 1
    for (int i = 0; i < nt; i++) {
        if (i + 1 < nt) asm volatile("cp.async.wait_group 1;" ::: "memory");
        else            asm volatile("cp.async.wait_group 0;" ::: "memory");
        __syncthreads();

        if (i == 0) {
            const uint32_t qoff = (w * 16 + (l & 15)) * 80 + ((l >> 4) * 8) * 2;
            LDSM4(qh[0], sQh + qoff);       LDSM4(qh[1], sQh + qoff + 32);
            LDSM4(ql[0], sQl + qoff);       LDSM4(ql[1], sQl + qoff + 32);
        }

        const uint32_t sb = smb + (i & 1) * AKV;
        const int key0 = i * 64;

        if (key0 <= qmax_w) {
            float s[8][4];
            #pragma unroll
            for (int n = 0; n < 8; n++)
                #pragma unroll
                for (int c = 0; c < 4; c++) s[n][c] = 0.0f;

            #pragma unroll
            for (int ks = 0; ks < 2; ks++) {
                #pragma unroll
                for (int g = 0; g < 4; g++) {
                    uint32_t kh[4], kl[4];
                    const uint32_t ka = sb
                        + (g * 16 + (l & 7) + ((l >> 4) & 1) * 8) * 80
                        + (ks * 16 + ((l >> 3) & 1) * 8) * 2;
                    LDSM4(kh, ka);
                    LDSM4(kl, ka + ATILE);
                    MMA16816(s[2*g],   qh[ks], kh[0], kh[1]);
                    MMA16816(s[2*g],   qh[ks], kl[0], kl[1]);
                    MMA16816(s[2*g],   ql[ks], kh[0], kh[1]);
                    MMA16816(s[2*g+1], qh[ks], kh[2], kh[3]);
                    MMA16816(s[2*g+1], qh[ks], kl[2], kl[3]);
                    MMA16816(s[2*g+1], ql[ks], kh[2], kh[3]);
                }
            }

            if (key0 + 63 > qmin_w) {
                #pragma unroll
                for (int n = 0; n < 8; n++) {
                    const int cb = key0 + n * 8 + (l & 3) * 2;
                    if (cb     > row0)     s[n][0] = -1e30f;
                    if (cb + 1 > row0)     s[n][1] = -1e30f;
                    if (cb     > row0 + 8) s[n][2] = -1e30f;
                    if (cb + 1 > row0 + 8) s[n][3] = -1e30f;
                }
            }

            uint32_t aPh[4][4], aPl[4][4];
            #pragma unroll
            for (int j = 0; j < 4; j++) {
                #pragma unroll
                for (int q = 0; q < 2; q++) {
                    const int n = 2 * j + q;
                    float p0, p1, p2, p3;
                    EX2(p0, s[n][0]);
                    EX2(p1, s[n][1]);
                    EX2(p2, s[n][2]);
                    EX2(p3, s[n][3]);
                    lp0 += p0 + p1; lp1 += p2 + p3;
                    uint32_t h01, h23;
                    PACKBF(h01, p0, p1);
                    PACKBF(h23, p2, p3);
                    aPh[j][2*q]   = h01;
                    aPh[j][2*q+1] = h23;
                    float f0 = __uint_as_float(h01 << 16);
                    float f1 = __uint_as_float(h01 & 0xffff0000u);
                    float f2 = __uint_as_float(h23 << 16);
                    float f3 = __uint_as_float(h23 & 0xffff0000u);
                    uint32_t l01, l23;
                    PACKBF(l01, p0 - f0, p1 - f1);
                    PACKBF(l23, p2 - f2, p3 - f3);
                    aPl[j][2*q]   = l01;
                    aPl[j][2*q+1] = l23;
                }
            }

            #pragma unroll
            for (int j = 0; j < 4; j++) {
                #pragma unroll
                for (int dg = 0; dg < 2; dg++) {
                    uint32_t vh[4], vl[4];
                    const uint32_t va = sb + 2 * ATILE
                        + (16 * j + (l & 7) + ((l >> 3) & 1) * 8) * 80
                        + (dg * 16 + ((l >> 4) & 1) * 8) * 2;
                    LDSM4T(vh, va);
                    LDSM4T(vl, va + ATILE);
                    MMA16816(O[2*dg],   aPh[j], vh[0], vh[1]);
                    MMA16816(O[2*dg],   aPh[j], vl[0], vl[1]);
                    MMA16816(O[2*dg],   aPl[j], vh[0], vh[1]);
                    MMA16816(O[2*dg+1], aPh[j], vh[2], vh[3]);
                    MMA16816(O[2*dg+1], aPh[j], vl[2], vl[3]);
                    MMA16816(O[2*dg+1], aPl[j], vh[2], vh[3]);
                }
            }
        }

        __syncthreads();
        if (i + 2 < nt)
            a_load_kv(sb, kh_g, kl_g, vh_g, vl_g, t, (i + 2) * 64);
    }

    lp0 += __shfl_xor_sync(0xffffffffu, lp0, 1);
    lp0 += __shfl_xor_sync(0xffffffffu, lp0, 2);
    lp1 += __shfl_xor_sync(0xffffffffu, lp1, 1);
    lp1 += __shfl_xor_sync(0xffffffffu, lp1, 2);
    const float inv0 = 1.0f / lp0, inv1 = 1.0f / lp1;

    #pragma unroll
    for (int nd = 0; nd < 4; nd++) {
        const int col = half * 32 + nd * 8 + (l & 3) * 2;
        *(float2*)&g_a[((size_t)h * S_LEN + row0) * HD + col] =
            make_float2(O[nd][0] * inv0, O[nd][1] * inv0);
        *(float2*)&g_a[((size_t)h * S_LEN + row0 + 8) * HD + col] =
            make_float2(O[nd][2] * inv1, O[nd][3] * inv1);
    }
}

// -------- differential combine, per-token --------
__global__ __launch_bounds__(512) void combine2(const float* __restrict__ lambda_p)
{
    const int m = blockIdx.x, t = threadIdx.x;
    const int h = t >> 5, j = t & 31;
    const float lam = lambda_p[h];
    const float* ap = g_a + ((size_t)h * S_LEN + m) * HD;
    const float a1 = ap[j], a2 = ap[j + 32];
    const float y1 = a1 - lam * a2, y2 = a1 + lam * a2;
    const size_t o1 = (size_t)m * DIM + h * HD + j, o2 = o1 + 32;
    split_bf(y1, g_yhi, g_ylo, o1);
    split_bf(y2, g_yhi, g_ylo, o2);
}

extern "C" void kernel_launch(void* const* d_in, const int* in_sizes, int n_in,
                              void* d_out, int out_size)
{
    const float* x        = (const float*)d_in[0];
    const float* Wq       = (const float*)d_in[1];
    const float* Wk       = (const float*)d_in[2];
    const float* Wv       = (const float*)d_in[3];
    const float* Wg       = (const float*)d_in[4];
    const float* Wo       = (const float*)d_in[5];
    const float* q_gain   = (const float*)d_in[6];
    const float* lambda_p = (const float*)d_in[7];
    float* out = (float*)d_out;

    cudaFuncSetAttribute(gemm_hmma3, cudaFuncAttributeMaxDynamicSharedMemorySize, GSMEM);
    cudaFuncSetAttribute(attn_mma, cudaFuncAttributeMaxDynamicSharedMemorySize, ASMEM);

    float* qkvg_p;
    __nv_bfloat16 *xhi, *xlo, *whi, *wlo, *wohi, *wolo, *yhi, *ylo;
    cudaGetSymbolAddress((void**)&qkvg_p, g_qkvg);
    cudaGetSymbolAddress((void**)&xhi, g_xhi);   cudaGetSymbolAddress((void**)&xlo, g_xlo);
    cudaGetSymbolAddress((void**)&whi, g_whi);   cudaGetSymbolAddress((void**)&wlo, g_wlo);
    cudaGetSymbolAddress((void**)&wohi, g_wohi); cudaGetSymbolAddress((void**)&wolo, g_wolo);
    cudaGetSymbolAddress((void**)&yhi, g_yhi);   cudaGetSymbolAddress((void**)&ylo, g_ylo);

    conv_all<<<4864, 256>>>(x, Wq, Wk, Wv, Wg, Wo);
    rotab<<<256, 256>>>();
    gemm_hmma3<<<dim3(NTOT/128, S_LEN/128), 256, GSMEM>>>(xhi, xlo, whi, wlo, qkvg_p, NTOT);
    pp_qk<<<dim3(S_LEN, 5), 128>>>(q_gain);
    pp_vgate<<<S_LEN, 256>>>();
    attn_mma<<<dim3(S_LEN/128, NH, 2), 256, ASMEM>>>();
    combine2<<<S_LEN, 512>>>(lambda_p);
    gemm_hmma3<<<dim3(DIM/128, S_LEN/128), 256, GSMEM>>>(yhi, ylo, wohi, wolo, out, DIM);
}

// round 9
// speedup vs baseline: 7.9103x; 1.4193x over previous
#include <cuda_runtime.h>
#include <cuda_bf16.h>
#include <cuda_fp16.h>
#include <math.h>
#include <stdint.h>

#define S_LEN 2048
#define DIM 1024
#define NH 16
#define KVH 4
#define HD 64
#define NTOT 1792

__device__ float g_qkvg[S_LEN * NTOT];
__device__ float g_a[NH * S_LEN * HD];
__device__ float2 g_rot[S_LEN * 32];
__device__ __half g_xh[S_LEN * DIM];
__device__ __half g_wh[NTOT * DIM];
__device__ __half g_woh[DIM * DIM];
__device__ __half g_yh[S_LEN * DIM];
__device__ __nv_bfloat16 g_aqh[NH*2*S_LEN*32], g_aql[NH*2*S_LEN*32];
__device__ __nv_bfloat16 g_akh[KVH*2*S_LEN*32], g_akl[KVH*2*S_LEN*32];
__device__ __nv_bfloat16 g_avh[KVH*2*S_LEN*32], g_avl[KVH*2*S_LEN*32];

__device__ __forceinline__ uint32_t smem_u32(const void* p) {
    uint32_t a;
    asm("{ .reg .u64 t; cvta.to.shared.u64 t, %1; cvt.u32.u64 %0, t; }" : "=r"(a) : "l"(p));
    return a;
}
#define CP16(sm, gp) asm volatile("cp.async.cg.shared.global [%0], [%1], 16;" :: "r"(sm), "l"(gp))
#define LDSM4(r, addr) \
    asm volatile("ldmatrix.sync.aligned.m8n8.x4.shared.b16 {%0,%1,%2,%3}, [%4];" \
        : "=r"((r)[0]), "=r"((r)[1]), "=r"((r)[2]), "=r"((r)[3]) : "r"(addr))
#define LDSM4T(r, addr) \
    asm volatile("ldmatrix.sync.aligned.m8n8.x4.trans.shared.b16 {%0,%1,%2,%3}, [%4];" \
        : "=r"((r)[0]), "=r"((r)[1]), "=r"((r)[2]), "=r"((r)[3]) : "r"(addr))
#define MMA16816(d, a, b0, b1) \
    asm volatile("mma.sync.aligned.m16n8k16.row.col.f32.bf16.bf16.f32 " \
        "{%0,%1,%2,%3}, {%4,%5,%6,%7}, {%8,%9}, {%0,%1,%2,%3};" \
        : "+f"((d)[0]), "+f"((d)[1]), "+f"((d)[2]), "+f"((d)[3]) \
        : "r"((a)[0]), "r"((a)[1]), "r"((a)[2]), "r"((a)[3]), "r"(b0), "r"(b1))
#define MMAF16(d, a, b0, b1) \
    asm volatile("mma.sync.aligned.m16n8k16.row.col.f32.f16.f16.f32 " \
        "{%0,%1,%2,%3}, {%4,%5,%6,%7}, {%8,%9}, {%0,%1,%2,%3};" \
        : "+f"((d)[0]), "+f"((d)[1]), "+f"((d)[2]), "+f"((d)[3]) \
        : "r"((a)[0]), "r"((a)[1]), "r"((a)[2]), "r"((a)[3]), "r"(b0), "r"(b1))
#define PACKBF(r, a, b) asm("cvt.rn.bf16x2.f32 %0, %1, %2;" : "=r"(r) : "f"(b), "f"(a))
#define EX2(d, x) asm("ex2.approx.ftz.f32 %0, %1;" : "=f"(d) : "f"(x))

__device__ __forceinline__ void split_bf(float v, __nv_bfloat16* hi, __nv_bfloat16* lo,
                                         size_t o) {
    __nv_bfloat16 h = __float2bfloat16(v);
    hi[o] = h; lo[o] = __float2bfloat16(v - __bfloat162float(h));
}

// -------- fused fp32 -> fp16 conversion for all 6 tensors --------
__global__ __launch_bounds__(256) void conv_all(
    const float* __restrict__ x,  const float* __restrict__ Wq,
    const float* __restrict__ Wk, const float* __restrict__ Wv,
    const float* __restrict__ Wg, const float* __restrict__ Wo)
{
    const int i = blockIdx.x * 256 + threadIdx.x;   // float4 index < 1245184
    const float* s; __half* d;
    if (i < 524288)      { size_t j = (size_t)i * 4;            s = x  + j; d = g_xh + j; }
    else if (i < 786432) { size_t j = (size_t)(i - 524288) * 4; s = Wq + j; d = g_wh + j; }
    else if (i < 851968) { size_t j = (size_t)(i - 786432) * 4; s = Wk + j; d = g_wh + 1048576 + j; }
    else if (i < 917504) { size_t j = (size_t)(i - 851968) * 4; s = Wv + j; d = g_wh + 1310720 + j; }
    else if (i < 983040) { size_t j = (size_t)(i - 917504) * 4; s = Wg + j; d = g_wh + 1572864 + j; }
    else                 { size_t j = (size_t)(i - 983040) * 4; s = Wo + j; d = g_woh + j; }
    float4 v = *(const float4*)s;
    __half2 h0 = __floats2half2_rn(v.x, v.y);
    __half2 h1 = __floats2half2_rn(v.z, v.w);
    *(__half2*)d = h0; *(__half2*)(d + 2) = h1;
}

// -------- rotary table --------
__global__ __launch_bounds__(256) void rotab()
{
    const int i = blockIdx.x * 256 + threadIdx.x;
    const int m = i >> 5, t = i & 31;
    const float angle = ((float)(2 * t) / 64.0f) * 3.14159274101257324f;
    const float ang = (float)m * angle;
    double a = (double)ang;
    a -= rint(a * 0.15915494309189535) * 6.283185307179586;
    float c, sn;
    sincosf((float)a, &sn, &c);
    const float radius = 1.0f / (1.0f + (float)m * 0.01f);
    g_rot[i] = make_float2(c * radius, sn * radius);
}

// -------- fp16 HMMA GEMM: C[M,N] = A[M,K] @ B[N,K]^T, 3-stage --------
#define AST   18432                 // 128 rows * 144B
#define STG_B (2 * AST)             // A + B
#define GSMEM (3 * STG_B)           // 110592 -> 2 CTAs/SM

__device__ __forceinline__ void g_load_stage(
    uint32_t sb, const char* pA, const char* pB, int t, int s)
{
    const size_t gk = (size_t)s * 128;
    #pragma unroll
    for (int j = 0; j < 8; j++) {
        const int idx = t + 256 * j;
        const int arr = idx >> 10, rem = idx & 1023;
        const int row = rem >> 3, kc = rem & 7;
        const size_t go = (size_t)row * 2048 + gk + kc * 16;
        const uint32_t so = arr * AST + row * 144 + kc * 16;
        CP16(sb + so, (arr ? pB : pA) + go);
    }
    asm volatile("cp.async.commit_group;" ::: "memory");
}

__global__ __launch_bounds__(256) void gemm_f16(
    const __half* __restrict__ A, const __half* __restrict__ B,
    float* __restrict__ C, int ldc)
{
    extern __shared__ char sm[];
    const int t = threadIdx.x, wid = t >> 5, lane = t & 31;
    const int m0 = blockIdx.y * 128, nb = blockIdx.x * 128;
    const uint32_t smb = smem_u32(sm);

    const char* pA = (const char*)A + (size_t)m0 * 2048;
    const char* pB = (const char*)B + (size_t)nb * 2048;

    const int warp_m = (wid & 1) * 64;
    const int warp_n = (wid >> 1) * 32;
    const int a_m  = lane & 15;
    const int a_kb = lane >> 4;
    const int b_n  = (lane & 7) + ((lane >> 4) & 1) * 8;
    const int b_kb = (lane >> 3) & 1;

    float acc[4][4][4];
    #pragma unroll
    for (int im = 0; im < 4; im++)
        #pragma unroll
        for (int jn = 0; jn < 4; jn++)
            #pragma unroll
            for (int c = 0; c < 4; c++) acc[im][jn][c] = 0.0f;

    g_load_stage(smb,             pA, pB, t, 0);
    g_load_stage(smb + STG_B,     pA, pB, t, 1);
    g_load_stage(smb + 2 * STG_B, pA, pB, t, 2);

    int buf = 0;
    #pragma unroll 1
    for (int s = 0; s < 16; s++) {
        if (s < 14)       asm volatile("cp.async.wait_group 2;" ::: "memory");
        else if (s == 14) asm volatile("cp.async.wait_group 1;" ::: "memory");
        else              asm volatile("cp.async.wait_group 0;" ::: "memory");
        __syncthreads();

        const uint32_t sb = smb + buf * STG_B;
        #pragma unroll
        for (int kk = 0; kk < 4; kk++) {
            const uint32_t k0 = kk * 16;
            uint32_t a[4][4], b[2][4];
            const uint32_t aoff = (warp_m + a_m) * 144 + (k0 + a_kb * 8) * 2;
            #pragma unroll
            for (int im = 0; im < 4; im++)
                LDSM4(a[im], sb + aoff + im * (16 * 144));
            #pragma unroll
            for (int j2 = 0; j2 < 2; j2++) {
                const uint32_t boff = (warp_n + j2 * 16 + b_n) * 144 + (k0 + b_kb * 8) * 2;
                LDSM4(b[j2], sb + AST + boff);
            }
            #pragma unroll
            for (int im = 0; im < 4; im++)
                #pragma unroll
                for (int jn = 0; jn < 4; jn++) {
                    const int j2 = jn >> 1, jr = (jn & 1) * 2;
                    MMAF16(acc[im][jn], a[im], b[j2][jr], b[j2][jr + 1]);
                }
        }
        __syncthreads();
        if (s + 3 < 16) g_load_stage(sb, pA, pB, t, s + 3);
        buf = (buf == 2) ? 0 : buf + 1;
    }

    const int r0 = lane >> 2, c0 = (lane & 3) * 2;
    #pragma unroll
    for (int im = 0; im < 4; im++)
        #pragma unroll
        for (int jn = 0; jn < 4; jn++) {
            const int row = m0 + warp_m + im * 16 + r0;
            const int col = nb + warp_n + jn * 8 + c0;
            *(float2*)&C[(size_t)row * ldc + col] =
                make_float2(acc[im][jn][0], acc[im][jn][1]);
            *(float2*)&C[(size_t)(row + 8) * ldc + col] =
                make_float2(acc[im][jn][2], acc[im][jn][3]);
        }
}

// -------- postprocess q/k: grid (S, 5) x 128, warp = one unit --------
#define LOG2E 1.4426950408889634f
__global__ __launch_bounds__(128) void pp_qk(const float* __restrict__ q_gain)
{
    const int m = blockIdx.x;
    const int w = threadIdx.x >> 5, l = threadIdx.x & 31;
    const int unit = blockIdx.y * 4 + w;
    const float* row = g_qkvg + (size_t)m * NTOT;

    const bool isq = unit < 16;
    const int h = isq ? unit : unit - 16;
    const int col0 = isq ? h * HD : 1024 + h * HD;
    float x1 = row[col0 + l], x2 = row[col0 + l + 32];
    float ss = x1 * x1 + x2 * x2;
    #pragma unroll
    for (int o = 16; o > 0; o >>= 1) ss += __shfl_xor_sync(0xffffffffu, ss, o);
    const float rn = rsqrtf(ss * (1.0f / 64.0f) + 1.1920929e-7f);
    x1 *= rn; x2 *= rn;
    const float2 rc = g_rot[m * 32 + l];
    float y0 = x1 * rc.x + x2 * rc.y;
    float y1 = -x1 * rc.y + x2 * rc.x;
    const size_t o0 = ((size_t)(h * 2 + 0) * S_LEN + m) * 32 + l;
    const size_t o1 = ((size_t)(h * 2 + 1) * S_LEN + m) * 32 + l;
    if (isq) {
        const float gs = q_gain[h] * (0.17677669529663688f * LOG2E);
        y0 *= gs; y1 *= gs;
        split_bf(y0, g_aqh, g_aql, o0);
        split_bf(y1, g_aqh, g_aql, o1);
    } else {
        split_bf(y0, g_akh, g_akl, o0);
        split_bf(y1, g_akh, g_akl, o1);
    }
}

// -------- v-gate --------
__global__ __launch_bounds__(256) void pp_vgate()
{
    const int m = blockIdx.x, i = threadIdx.x;
    const float* row = g_qkvg + (size_t)m * NTOT;
    float v = row[1280 + i], g = row[1536 + i];
    float vg = v / (1.0f + __expf(-g));
    int kvh = i >> 6, d = i & 63, hf = d >> 5, dc = d & 31;
    size_t o = ((size_t)(kvh * 2 + hf) * S_LEN + m) * 32 + dc;
    split_bf(vg, g_avh, g_avl, o);
}

// -------- HMMA flash attention (fixed-base exp2 softmax, bf16x3) --------
#define ATILE 5120
#define QTILE 10240
#define AKV   (4 * ATILE)
#define ASMEM (2 * AKV + 2 * QTILE)    // 61440

__device__ __forceinline__ void a_load_kv(
    uint32_t sb, const char* kh, const char* kl,
    const char* vh, const char* vl, int t, int key0)
{
    const char* base[4] = { kh, kl, vh, vl };
    #pragma unroll
    for (int j = 0; j < 4; j++) {
        const int c = t + 256 * j;
        const int arr = c >> 8, rem = c & 255;
        const int row = rem >> 2, c4 = rem & 3;
        CP16(sb + arr * ATILE + row * 80 + c4 * 16,
             base[arr] + ((size_t)(key0 + row) * 32 + c4 * 8) * 2);
    }
    asm volatile("cp.async.commit_group;" ::: "memory");
}

__global__ __launch_bounds__(256) void attn_mma()
{
    extern __shared__ char sm[];
    const int qt = gridDim.x - 1 - blockIdx.x;
    const int h = blockIdx.y, half = blockIdx.z, kvh = h >> 2;
    const int t = threadIdx.x, w = t >> 5, l = t & 31;
    const int q0 = qt * 128;
    const uint32_t smb = smem_u32(sm);
    const uint32_t sQh = smb + 2 * AKV, sQl = sQh + QTILE;

    const char* qh_g = (const char*)(g_aqh + ((size_t)(h * 2 + half) * S_LEN + q0) * 32);
    const char* ql_g = (const char*)(g_aql + ((size_t)(h * 2 + half) * S_LEN + q0) * 32);
    const char* kh_g = (const char*)(g_akh + (size_t)(kvh * 2 + half) * S_LEN * 32);
    const char* kl_g = (const char*)(g_akl + (size_t)(kvh * 2 + half) * S_LEN * 32);
    const char* vh_g = (const char*)(g_avh + (size_t)(kvh * 2 + half) * S_LEN * 32);
    const char* vl_g = (const char*)(g_avl + (size_t)(kvh * 2 + half) * S_LEN * 32);

    #pragma unroll
    for (int j = 0; j < 4; j++) {
        const int c = t + 256 * j;
        const int arr = c >> 9, rem = c & 511;
        const int row = rem >> 2, c4 = rem & 3;
        CP16((arr ? sQl : sQh) + row * 80 + c4 * 16,
             (arr ? ql_g : qh_g) + ((size_t)row * 32 + c4 * 8) * 2);
    }
    a_load_kv(smb, kh_g, kl_g, vh_g, vl_g, t, 0);
    const int nt = 2 * qt + 2;
    if (nt > 1) a_load_kv(smb + AKV, kh_g, kl_g, vh_g, vl_g, t, 64);

    uint32_t qh[2][4], ql[2][4];
    float O[4][4];
    #pragma unroll
    for (int nd = 0; nd < 4; nd++)
        #pragma unroll
        for (int c = 0; c < 4; c++) O[nd][c] = 0.0f;
    float lp0 = 0.0f, lp1 = 0.0f;

    const int row0 = q0 + w * 16 + (l >> 2);
    const int qmax_w = q0 + w * 16 + 15;
    const int qmin_w = q0 + w * 16;

    #pragma unroll 1
    for (int i = 0; i < nt; i++) {
        if (i + 1 < nt) asm volatile("cp.async.wait_group 1;" ::: "memory");
        else            asm volatile("cp.async.wait_group 0;" ::: "memory");
        __syncthreads();

        if (i == 0) {
            const uint32_t qoff = (w * 16 + (l & 15)) * 80 + ((l >> 4) * 8) * 2;
            LDSM4(qh[0], sQh + qoff);       LDSM4(qh[1], sQh + qoff + 32);
            LDSM4(ql[0], sQl + qoff);       LDSM4(ql[1], sQl + qoff + 32);
        }

        const uint32_t sb = smb + (i & 1) * AKV;
        const int key0 = i * 64;

        if (key0 <= qmax_w) {
            float s[8][4];
            #pragma unroll
            for (int n = 0; n < 8; n++)
                #pragma unroll
                for (int c = 0; c < 4; c++) s[n][c] = 0.0f;

            #pragma unroll
            for (int ks = 0; ks < 2; ks++) {
                #pragma unroll
                for (int g = 0; g < 4; g++) {
                    uint32_t kh[4], kl[4];
                    const uint32_t ka = sb
                        + (g * 16 + (l & 7) + ((l >> 4) & 1) * 8) * 80
                        + (ks * 16 + ((l >> 3) & 1) * 8) * 2;
                    LDSM4(kh, ka);
                    LDSM4(kl, ka + ATILE);
                    MMA16816(s[2*g],   qh[ks], kh[0], kh[1]);
                    MMA16816(s[2*g],   qh[ks], kl[0], kl[1]);
                    MMA16816(s[2*g],   ql[ks], kh[0], kh[1]);
                    MMA16816(s[2*g+1], qh[ks], kh[2], kh[3]);
                    MMA16816(s[2*g+1], qh[ks], kl[2], kl[3]);
                    MMA16816(s[2*g+1], ql[ks], kh[2], kh[3]);
                }
            }

            if (key0 + 63 > qmin_w) {
                #pragma unroll
                for (int n = 0; n < 8; n++) {
                    const int cb = key0 + n * 8 + (l & 3) * 2;
                    if (cb     > row0)     s[n][0] = -1e30f;
                    if (cb + 1 > row0)     s[n][1] = -1e30f;
                    if (cb     > row0 + 8) s[n][2] = -1e30f;
                    if (cb + 1 > row0 + 8) s[n][3] = -1e30f;
                }
            }

            uint32_t aPh[4][4], aPl[4][4];
            #pragma unroll
            for (int j = 0; j < 4; j++) {
                #pragma unroll
                for (int q = 0; q < 2; q++) {
                    const int n = 2 * j + q;
                    float p0, p1, p2, p3;
                    EX2(p0, s[n][0]);
                    EX2(p1, s[n][1]);
                    EX2(p2, s[n][2]);
                    EX2(p3, s[n][3]);
                    lp0 += p0 + p1; lp1 += p2 + p3;
                    uint32_t h01, h23;
                    PACKBF(h01, p0, p1);
                    PACKBF(h23, p2, p3);
                    aPh[j][2*q]   = h01;
                    aPh[j][2*q+1] = h23;
                    float f0 = __uint_as_float(h01 << 16);
                    float f1 = __uint_as_float(h01 & 0xffff0000u);
                    float f2 = __uint_as_float(h23 << 16);
                    float f3 = __uint_as_float(h23 & 0xffff0000u);
                    uint32_t l01, l23;
                    PACKBF(l01, p0 - f0, p1 - f1);
                    PACKBF(l23, p2 - f2, p3 - f3);
                    aPl[j][2*q]   = l01;
                    aPl[j][2*q+1] = l23;
                }
            }

            #pragma unroll
            for (int j = 0; j < 4; j++) {
                #pragma unroll
                for (int dg = 0; dg < 2; dg++) {
                    uint32_t vh[4], vl[4];
                    const uint32_t va = sb + 2 * ATILE
                        + (16 * j + (l & 7) + ((l >> 3) & 1) * 8) * 80
                        + (dg * 16 + ((l >> 4) & 1) * 8) * 2;
                    LDSM4T(vh, va);
                    LDSM4T(vl, va + ATILE);
                    MMA16816(O[2*dg],   aPh[j], vh[0], vh[1]);
                    MMA16816(O[2*dg],   aPh[j], vl[0], vl[1]);
                    MMA16816(O[2*dg],   aPl[j], vh[0], vh[1]);
                    MMA16816(O[2*dg+1], aPh[j], vh[2], vh[3]);
                    MMA16816(O[2*dg+1], aPh[j], vl[2], vl[3]);
                    MMA16816(O[2*dg+1], aPl[j], vh[2], vh[3]);
                }
            }
        }

        __syncthreads();
        if (i + 2 < nt)
            a_load_kv(sb, kh_g, kl_g, vh_g, vl_g, t, (i + 2) * 64);
    }

    lp0 += __shfl_xor_sync(0xffffffffu, lp0, 1);
    lp0 += __shfl_xor_sync(0xffffffffu, lp0, 2);
    lp1 += __shfl_xor_sync(0xffffffffu, lp1, 1);
    lp1 += __shfl_xor_sync(0xffffffffu, lp1, 2);
    const float inv0 = 1.0f / lp0, inv1 = 1.0f / lp1;

    #pragma unroll
    for (int nd = 0; nd < 4; nd++) {
        const int col = half * 32 + nd * 8 + (l & 3) * 2;
        *(float2*)&g_a[((size_t)h * S_LEN + row0) * HD + col] =
            make_float2(O[nd][0] * inv0, O[nd][1] * inv0);
        *(float2*)&g_a[((size_t)h * S_LEN + row0 + 8) * HD + col] =
            make_float2(O[nd][2] * inv1, O[nd][3] * inv1);
    }
}

// -------- differential combine -> fp16 --------
__global__ __launch_bounds__(512) void combine2(const float* __restrict__ lambda_p)
{
    const int m = blockIdx.x, t = threadIdx.x;
    const int h = t >> 5, j = t & 31;
    const float lam = lambda_p[h];
    const float* ap = g_a + ((size_t)h * S_LEN + m) * HD;
    const float a1 = ap[j], a2 = ap[j + 32];
    const size_t o1 = (size_t)m * DIM + h * HD + j;
    g_yh[o1]      = __float2half_rn(a1 - lam * a2);
    g_yh[o1 + 32] = __float2half_rn(a1 + lam * a2);
}

extern "C" void kernel_launch(void* const* d_in, const int* in_sizes, int n_in,
                              void* d_out, int out_size)
{
    const float* x        = (const float*)d_in[0];
    const float* Wq       = (const float*)d_in[1];
    const float* Wk       = (const float*)d_in[2];
    const float* Wv       = (const float*)d_in[3];
    const float* Wg       = (const float*)d_in[4];
    const float* Wo       = (const float*)d_in[5];
    const float* q_gain   = (const float*)d_in[6];
    const float* lambda_p = (const float*)d_in[7];
    float* out = (float*)d_out;

    cudaFuncSetAttribute(gemm_f16, cudaFuncAttributeMaxDynamicSharedMemorySize, GSMEM);
    cudaFuncSetAttribute(attn_mma, cudaFuncAttributeMaxDynamicSharedMemorySize, ASMEM);

    float* qkvg_p;
    __half *xh, *wh, *woh, *yh;
    cudaGetSymbolAddress((void**)&qkvg_p, g_qkvg);
    cudaGetSymbolAddress((void**)&xh, g_xh);
    cudaGetSymbolAddress((void**)&wh, g_wh);
    cudaGetSymbolAddress((void**)&woh, g_woh);
    cudaGetSymbolAddress((void**)&yh, g_yh);

    conv_all<<<4864, 256>>>(x, Wq, Wk, Wv, Wg, Wo);
    rotab<<<256, 256>>>();
    gemm_f16<<<dim3(NTOT/128, S_LEN/128), 256, GSMEM>>>(xh, wh, qkvg_p, NTOT);
    pp_qk<<<dim3(S_LEN, 5), 128>>>(q_gain);
    pp_vgate<<<S_LEN, 256>>>();
    attn_mma<<<dim3(S_LEN/128, NH, 2), 256, ASMEM>>>();
    combine2<<<S_LEN, 512>>>(lambda_p);
    gemm_f16<<<dim3(DIM/128, S_LEN/128), 256, GSMEM>>>(yh, woh, out, DIM);
}

// round 10
// speedup vs baseline: 11.3093x; 1.4297x over previous
#include <cuda_runtime.h>
#include <cuda_bf16.h>
#include <cuda_fp16.h>
#include <math.h>
#include <stdint.h>

#define S_LEN 2048
#define DIM 1024
#define NH 16
#define KVH 4
#define HD 64
#define NTOT 1792

__device__ float g_qkvg[S_LEN * NTOT];
__device__ float g_a[NH * S_LEN * HD];
__device__ float2 g_rot[S_LEN * 32];
__device__ __half g_xh[S_LEN * DIM];
__device__ __half g_wh[NTOT * DIM];
__device__ __half g_woh[DIM * DIM];
__device__ __half g_yh[S_LEN * DIM];
// attention operands: q fp16 hi/lo, k/v single fp16; layout [(head*2+half)][seq][32]
__device__ __half g_aqh[NH*2*S_LEN*32], g_aql[NH*2*S_LEN*32];
__device__ __half g_ak[KVH*2*S_LEN*32];
__device__ __half g_av[KVH*2*S_LEN*32];

__device__ __forceinline__ uint32_t smem_u32(const void* p) {
    uint32_t a;
    asm("{ .reg .u64 t; cvta.to.shared.u64 t, %1; cvt.u32.u64 %0, t; }" : "=r"(a) : "l"(p));
    return a;
}
#define CP16(sm, gp) asm volatile("cp.async.cg.shared.global [%0], [%1], 16;" :: "r"(sm), "l"(gp))
#define LDSM4(r, addr) \
    asm volatile("ldmatrix.sync.aligned.m8n8.x4.shared.b16 {%0,%1,%2,%3}, [%4];" \
        : "=r"((r)[0]), "=r"((r)[1]), "=r"((r)[2]), "=r"((r)[3]) : "r"(addr))
#define LDSM4T(r, addr) \
    asm volatile("ldmatrix.sync.aligned.m8n8.x4.trans.shared.b16 {%0,%1,%2,%3}, [%4];" \
        : "=r"((r)[0]), "=r"((r)[1]), "=r"((r)[2]), "=r"((r)[3]) : "r"(addr))
#define MMAF16(d, a, b0, b1) \
    asm volatile("mma.sync.aligned.m16n8k16.row.col.f32.f16.f16.f32 " \
        "{%0,%1,%2,%3}, {%4,%5,%6,%7}, {%8,%9}, {%0,%1,%2,%3};" \
        : "+f"((d)[0]), "+f"((d)[1]), "+f"((d)[2]), "+f"((d)[3]) \
        : "r"((a)[0]), "r"((a)[1]), "r"((a)[2]), "r"((a)[3]), "r"(b0), "r"(b1))
#define PACKF16(r, a, b) asm("cvt.rn.f16x2.f32 %0, %1, %2;" : "=r"(r) : "f"(b), "f"(a))
#define EX2(d, x) asm("ex2.approx.ftz.f32 %0, %1;" : "=f"(d) : "f"(x))

__device__ __forceinline__ void split_f16(float v, __half* hi, __half* lo, size_t o) {
    __half h = __float2half_rn(v);
    hi[o] = h; lo[o] = __float2half_rn(v - __half2float(h));
}

// -------- fused fp32 -> fp16 conversion for all 6 tensors --------
__global__ __launch_bounds__(256) void conv_all(
    const float* __restrict__ x,  const float* __restrict__ Wq,
    const float* __restrict__ Wk, const float* __restrict__ Wv,
    const float* __restrict__ Wg, const float* __restrict__ Wo)
{
    const int i = blockIdx.x * 256 + threadIdx.x;
    const float* s; __half* d;
    if (i < 524288)      { size_t j = (size_t)i * 4;            s = x  + j; d = g_xh + j; }
    else if (i < 786432) { size_t j = (size_t)(i - 524288) * 4; s = Wq + j; d = g_wh + j; }
    else if (i < 851968) { size_t j = (size_t)(i - 786432) * 4; s = Wk + j; d = g_wh + 1048576 + j; }
    else if (i < 917504) { size_t j = (size_t)(i - 851968) * 4; s = Wv + j; d = g_wh + 1310720 + j; }
    else if (i < 983040) { size_t j = (size_t)(i - 917504) * 4; s = Wg + j; d = g_wh + 1572864 + j; }
    else                 { size_t j = (size_t)(i - 983040) * 4; s = Wo + j; d = g_woh + j; }
    float4 v = *(const float4*)s;
    __half2 h0 = __floats2half2_rn(v.x, v.y);
    __half2 h1 = __floats2half2_rn(v.z, v.w);
    *(__half2*)d = h0; *(__half2*)(d + 2) = h1;
}

// -------- rotary table --------
__global__ __launch_bounds__(256) void rotab()
{
    const int i = blockIdx.x * 256 + threadIdx.x;
    const int m = i >> 5, t = i & 31;
    const float angle = ((float)(2 * t) / 64.0f) * 3.14159274101257324f;
    const float ang = (float)m * angle;
    double a = (double)ang;
    a -= rint(a * 0.15915494309189535) * 6.283185307179586;
    float c, sn;
    sincosf((float)a, &sn, &c);
    const float radius = 1.0f / (1.0f + (float)m * 0.01f);
    g_rot[i] = make_float2(c * radius, sn * radius);
}

// -------- fp16 HMMA GEMM: C[M,N] = A[M,K] @ B[N,K]^T, 3-stage --------
#define AST   18432
#define STG_B (2 * AST)
#define GSMEM (3 * STG_B)           // 110592

__device__ __forceinline__ void g_load_stage(
    uint32_t sb, const char* pA, const char* pB, int t, int s)
{
    const size_t gk = (size_t)s * 128;
    #pragma unroll
    for (int j = 0; j < 8; j++) {
        const int idx = t + 256 * j;
        const int arr = idx >> 10, rem = idx & 1023;
        const int row = rem >> 3, kc = rem & 7;
        const size_t go = (size_t)row * 2048 + gk + kc * 16;
        const uint32_t so = arr * AST + row * 144 + kc * 16;
        CP16(sb + so, (arr ? pB : pA) + go);
    }
    asm volatile("cp.async.commit_group;" ::: "memory");
}

__global__ __launch_bounds__(256) void gemm_f16(
    const __half* __restrict__ A, const __half* __restrict__ B,
    float* __restrict__ C, int ldc)
{
    extern __shared__ char sm[];
    const int t = threadIdx.x, wid = t >> 5, lane = t & 31;
    const int m0 = blockIdx.y * 128, nb = blockIdx.x * 128;
    const uint32_t smb = smem_u32(sm);

    const char* pA = (const char*)A + (size_t)m0 * 2048;
    const char* pB = (const char*)B + (size_t)nb * 2048;

    const int warp_m = (wid & 1) * 64;
    const int warp_n = (wid >> 1) * 32;
    const int a_m  = lane & 15;
    const int a_kb = lane >> 4;
    const int b_n  = (lane & 7) + ((lane >> 4) & 1) * 8;
    const int b_kb = (lane >> 3) & 1;

    float acc[4][4][4];
    #pragma unroll
    for (int im = 0; im < 4; im++)
        #pragma unroll
        for (int jn = 0; jn < 4; jn++)
            #pragma unroll
            for (int c = 0; c < 4; c++) acc[im][jn][c] = 0.0f;

    g_load_stage(smb,             pA, pB, t, 0);
    g_load_stage(smb + STG_B,     pA, pB, t, 1);
    g_load_stage(smb + 2 * STG_B, pA, pB, t, 2);

    int buf = 0;
    #pragma unroll 1
    for (int s = 0; s < 16; s++) {
        if (s < 14)       asm volatile("cp.async.wait_group 2;" ::: "memory");
        else if (s == 14) asm volatile("cp.async.wait_group 1;" ::: "memory");
        else              asm volatile("cp.async.wait_group 0;" ::: "memory");
        __syncthreads();

        const uint32_t sb = smb + buf * STG_B;
        #pragma unroll
        for (int kk = 0; kk < 4; kk++) {
            const uint32_t k0 = kk * 16;
            uint32_t a[4][4], b[2][4];
            const uint32_t aoff = (warp_m + a_m) * 144 + (k0 + a_kb * 8) * 2;
            #pragma unroll
            for (int im = 0; im < 4; im++)
                LDSM4(a[im], sb + aoff + im * (16 * 144));
            #pragma unroll
            for (int j2 = 0; j2 < 2; j2++) {
                const uint32_t boff = (warp_n + j2 * 16 + b_n) * 144 + (k0 + b_kb * 8) * 2;
                LDSM4(b[j2], sb + AST + boff);
            }
            #pragma unroll
            for (int im = 0; im < 4; im++)
                #pragma unroll
                for (int jn = 0; jn < 4; jn++) {
                    const int j2 = jn >> 1, jr = (jn & 1) * 2;
                    MMAF16(acc[im][jn], a[im], b[j2][jr], b[j2][jr + 1]);
                }
        }
        __syncthreads();
        if (s + 3 < 16) g_load_stage(sb, pA, pB, t, s + 3);
        buf = (buf == 2) ? 0 : buf + 1;
    }

    const int r0 = lane >> 2, c0 = (lane & 3) * 2;
    #pragma unroll
    for (int im = 0; im < 4; im++)
        #pragma unroll
        for (int jn = 0; jn < 4; jn++) {
            const int row = m0 + warp_m + im * 16 + r0;
            const int col = nb + warp_n + jn * 8 + c0;
            *(float2*)&C[(size_t)row * ldc + col] =
                make_float2(acc[im][jn][0], acc[im][jn][1]);
            *(float2*)&C[(size_t)(row + 8) * ldc + col] =
                make_float2(acc[im][jn][2], acc[im][jn][3]);
        }
}

// -------- postprocess q/k --------
#define LOG2E 1.4426950408889634f
__global__ __launch_bounds__(128) void pp_qk(const float* __restrict__ q_gain)
{
    const int m = blockIdx.x;
    const int w = threadIdx.x >> 5, l = threadIdx.x & 31;
    const int unit = blockIdx.y * 4 + w;
    const float* row = g_qkvg + (size_t)m * NTOT;

    const bool isq = unit < 16;
    const int h = isq ? unit : unit - 16;
    const int col0 = isq ? h * HD : 1024 + h * HD;
    float x1 = row[col0 + l], x2 = row[col0 + l + 32];
    float ss = x1 * x1 + x2 * x2;
    #pragma unroll
    for (int o = 16; o > 0; o >>= 1) ss += __shfl_xor_sync(0xffffffffu, ss, o);
    const float rn = rsqrtf(ss * (1.0f / 64.0f) + 1.1920929e-7f);
    x1 *= rn; x2 *= rn;
    const float2 rc = g_rot[m * 32 + l];
    float y0 = x1 * rc.x + x2 * rc.y;
    float y1 = -x1 * rc.y + x2 * rc.x;
    const size_t o0 = ((size_t)(h * 2 + 0) * S_LEN + m) * 32 + l;
    const size_t o1 = ((size_t)(h * 2 + 1) * S_LEN + m) * 32 + l;
    if (isq) {
        const float gs = q_gain[h] * (0.17677669529663688f * LOG2E);
        y0 *= gs; y1 *= gs;
        split_f16(y0, g_aqh, g_aql, o0);
        split_f16(y1, g_aqh, g_aql, o1);
    } else {
        g_ak[o0] = __float2half_rn(y0);
        g_ak[o1] = __float2half_rn(y1);
    }
}

// -------- v-gate --------
__global__ __launch_bounds__(256) void pp_vgate()
{
    const int m = blockIdx.x, i = threadIdx.x;
    const float* row = g_qkvg + (size_t)m * NTOT;
    float v = row[1280 + i], g = row[1536 + i];
    float vg = v / (1.0f + __expf(-g));
    int kvh = i >> 6, d = i & 63, hf = d >> 5, dc = d & 31;
    size_t o = ((size_t)(kvh * 2 + hf) * S_LEN + m) * 32 + dc;
    g_av[o] = __float2half_rn(vg);
}

// -------- HMMA flash attention: fp16 QK(2-MMA) + PV(1-MMA) --------
#define ATILE 5120                     // 64 rows * 80B
#define QTILE 10240                    // 128 rows * 80B
#define AKV   (2 * ATILE)              // k, v (single fp16)
#define ASMEM (2 * AKV + 2 * QTILE)    // 40960

__device__ __forceinline__ void a_load_kv(
    uint32_t sb, const char* kp, const char* vp, int t, int key0)
{
    #pragma unroll
    for (int j = 0; j < 2; j++) {
        const int c = t + 256 * j;              // 0..511
        const int arr = c >> 8, rem = c & 255;
        const int row = rem >> 2, c4 = rem & 3;
        CP16(sb + arr * ATILE + row * 80 + c4 * 16,
             (arr ? vp : kp) + ((size_t)(key0 + row) * 32 + c4 * 8) * 2);
    }
    asm volatile("cp.async.commit_group;" ::: "memory");
}

__global__ __launch_bounds__(256) void attn_mma()
{
    extern __shared__ char sm[];
    const int qt = gridDim.x - 1 - blockIdx.x;
    const int h = blockIdx.y, half = blockIdx.z, kvh = h >> 2;
    const int t = threadIdx.x, w = t >> 5, l = t & 31;
    const int q0 = qt * 128;
    const uint32_t smb = smem_u32(sm);
    const uint32_t sQh = smb + 2 * AKV, sQl = sQh + QTILE;

    const char* qh_g = (const char*)(g_aqh + ((size_t)(h * 2 + half) * S_LEN + q0) * 32);
    const char* ql_g = (const char*)(g_aql + ((size_t)(h * 2 + half) * S_LEN + q0) * 32);
    const char* k_g  = (const char*)(g_ak + (size_t)(kvh * 2 + half) * S_LEN * 32);
    const char* v_g  = (const char*)(g_av + (size_t)(kvh * 2 + half) * S_LEN * 32);

    // Q (hi/lo, 128 rows x 4 chunks x 2 arrays = 1024 CP16s)
    #pragma unroll
    for (int j = 0; j < 4; j++) {
        const int c = t + 256 * j;
        const int arr = c >> 9, rem = c & 511;
        const int row = rem >> 2, c4 = rem & 3;
        CP16((arr ? sQl : sQh) + row * 80 + c4 * 16,
             (arr ? ql_g : qh_g) + ((size_t)row * 32 + c4 * 8) * 2);
    }
    a_load_kv(smb, k_g, v_g, t, 0);
    const int nt = 2 * qt + 2;
    if (nt > 1) a_load_kv(smb + AKV, k_g, v_g, t, 64);

    uint32_t qh[2][4], ql[2][4];
    float O[4][4];
    #pragma unroll
    for (int nd = 0; nd < 4; nd++)
        #pragma unroll
        for (int c = 0; c < 4; c++) O[nd][c] = 0.0f;
    float lp0 = 0.0f, lp1 = 0.0f;

    const int row0 = q0 + w * 16 + (l >> 2);
    const int qmax_w = q0 + w * 16 + 15;
    const int qmin_w = q0 + w * 16;

    #pragma unroll 1
    for (int i = 0; i < nt; i++) {
        if (i + 1 < nt) asm volatile("cp.async.wait_group 1;" ::: "memory");
        else            asm volatile("cp.async.wait_group 0;" ::: "memory");
        __syncthreads();

        if (i == 0) {
            const uint32_t qoff = (w * 16 + (l & 15)) * 80 + ((l >> 4) * 8) * 2;
            LDSM4(qh[0], sQh + qoff);       LDSM4(qh[1], sQh + qoff + 32);
            LDSM4(ql[0], sQl + qoff);       LDSM4(ql[1], sQl + qoff + 32);
        }

        const uint32_t sb = smb + (i & 1) * AKV;
        const int key0 = i * 64;

        if (key0 <= qmax_w) {
            float s[8][4];
            #pragma unroll
            for (int n = 0; n < 8; n++)
                #pragma unroll
                for (int c = 0; c < 4; c++) s[n][c] = 0.0f;

            #pragma unroll
            for (int ks = 0; ks < 2; ks++) {
                #pragma unroll
                for (int g = 0; g < 4; g++) {
                    uint32_t kf[4];
                    const uint32_t ka = sb
                        + (g * 16 + (l & 7) + ((l >> 4) & 1) * 8) * 80
                        + (ks * 16 + ((l >> 3) & 1) * 8) * 2;
                    LDSM4(kf, ka);
                    MMAF16(s[2*g],   qh[ks], kf[0], kf[1]);
                    MMAF16(s[2*g],   ql[ks], kf[0], kf[1]);
                    MMAF16(s[2*g+1], qh[ks], kf[2], kf[3]);
                    MMAF16(s[2*g+1], ql[ks], kf[2], kf[3]);
                }
            }

            if (key0 + 63 > qmin_w) {
                #pragma unroll
                for (int n = 0; n < 8; n++) {
                    const int cb = key0 + n * 8 + (l & 3) * 2;
                    if (cb     > row0)     s[n][0] = -1e30f;
                    if (cb + 1 > row0)     s[n][1] = -1e30f;
                    if (cb     > row0 + 8) s[n][2] = -1e30f;
                    if (cb + 1 > row0 + 8) s[n][3] = -1e30f;
                }
            }

            // fixed-base softmax; p packed single fp16 for PV
            uint32_t aP[4][4];
            #pragma unroll
            for (int j = 0; j < 4; j++) {
                #pragma unroll
                for (int q = 0; q < 2; q++) {
                    const int n = 2 * j + q;
                    float p0, p1, p2, p3;
                    EX2(p0, s[n][0]);
                    EX2(p1, s[n][1]);
                    EX2(p2, s[n][2]);
                    EX2(p3, s[n][3]);
                    lp0 += p0 + p1; lp1 += p2 + p3;
                    PACKF16(aP[j][2*q],     p0, p1);
                    PACKF16(aP[j][2*q + 1], p2, p3);
                }
            }

            #pragma unroll
            for (int j = 0; j < 4; j++) {
                #pragma unroll
                for (int dg = 0; dg < 2; dg++) {
                    uint32_t vf[4];
                    const uint32_t va = sb + ATILE
                        + (16 * j + (l & 7) + ((l >> 3) & 1) * 8) * 80
                        + (dg * 16 + ((l >> 4) & 1) * 8) * 2;
                    LDSM4T(vf, va);
                    MMAF16(O[2*dg],     aP[j], vf[0], vf[1]);
                    MMAF16(O[2*dg + 1], aP[j], vf[2], vf[3]);
                }
            }
        }

        __syncthreads();
        if (i + 2 < nt)
            a_load_kv(sb, k_g, v_g, t, (i + 2) * 64);
    }

    lp0 += __shfl_xor_sync(0xffffffffu, lp0, 1);
    lp0 += __shfl_xor_sync(0xffffffffu, lp0, 2);
    lp1 += __shfl_xor_sync(0xffffffffu, lp1, 1);
    lp1 += __shfl_xor_sync(0xffffffffu, lp1, 2);
    const float inv0 = 1.0f / lp0, inv1 = 1.0f / lp1;

    #pragma unroll
    for (int nd = 0; nd < 4; nd++) {
        const int col = half * 32 + nd * 8 + (l & 3) * 2;
        *(float2*)&g_a[((size_t)h * S_LEN + row0) * HD + col] =
            make_float2(O[nd][0] * inv0, O[nd][1] * inv0);
        *(float2*)&g_a[((size_t)h * S_LEN + row0 + 8) * HD + col] =
            make_float2(O[nd][2] * inv1, O[nd][3] * inv1);
    }
}

// -------- differential combine -> fp16 --------
__global__ __launch_bounds__(512) void combine2(const float* __restrict__ lambda_p)
{
    const int m = blockIdx.x, t = threadIdx.x;
    const int h = t >> 5, j = t & 31;
    const float lam = lambda_p[h];
    const float* ap = g_a + ((size_t)h * S_LEN + m) * HD;
    const float a1 = ap[j], a2 = ap[j + 32];
    const size_t o1 = (size_t)m * DIM + h * HD + j;
    g_yh[o1]      = __float2half_rn(a1 - lam * a2);
    g_yh[o1 + 32] = __float2half_rn(a1 + lam * a2);
}

extern "C" void kernel_launch(void* const* d_in, const int* in_sizes, int n_in,
                              void* d_out, int out_size)
{
    const float* x        = (const float*)d_in[0];
    const float* Wq       = (const float*)d_in[1];
    const float* Wk       = (const float*)d_in[2];
    const float* Wv       = (const float*)d_in[3];
    const float* Wg       = (const float*)d_in[4];
    const float* Wo       = (const float*)d_in[5];
    const float* q_gain   = (const float*)d_in[6];
    const float* lambda_p = (const float*)d_in[7];
    float* out = (float*)d_out;

    cudaFuncSetAttribute(gemm_f16, cudaFuncAttributeMaxDynamicSharedMemorySize, GSMEM);
    cudaFuncSetAttribute(attn_mma, cudaFuncAttributeMaxDynamicSharedMemorySize, ASMEM);

    float* qkvg_p;
    __half *xh, *wh, *woh, *yh;
    cudaGetSymbolAddress((void**)&qkvg_p, g_qkvg);
    cudaGetSymbolAddress((void**)&xh, g_xh);
    cudaGetSymbolAddress((void**)&wh, g_wh);
    cudaGetSymbolAddress((void**)&woh, g_woh);
    cudaGetSymbolAddress((void**)&yh, g_yh);

    conv_all<<<4864, 256>>>(x, Wq, Wk, Wv, Wg, Wo);
    rotab<<<256, 256>>>();
    gemm_f16<<<dim3(NTOT/128, S_LEN/128), 256, GSMEM>>>(xh, wh, qkvg_p, NTOT);
    pp_qk<<<dim3(S_LEN, 5), 128>>>(q_gain);
    pp_vgate<<<S_LEN, 256>>>();
    attn_mma<<<dim3(S_LEN/128, NH, 2), 256, ASMEM>>>();
    combine2<<<S_LEN, 512>>>(lambda_p);
    gemm_f16<<<dim3(DIM/128, S_LEN/128), 256, GSMEM>>>(yh, woh, out, DIM);
}